// round 1
// baseline (speedup 1.0000x reference)
#include <cuda_runtime.h>
#include <math.h>

static constexpr int cB  = 2;
static constexpr int cS  = 2048;
static constexpr int cD  = 1024;
static constexpr int cH  = 16;
static constexpr int cDK = 64;
static constexpr int cM  = cB * cS;   // 4096

// Scratch (allocation-free): q/k/v head-split [B,H,S,DK], ctx [M,D]
__device__ float g_q[cB*cH*cS*cDK];
__device__ float g_k[cB*cH*cS*cDK];
__device__ float g_v[cB*cH*cS*cDK];
__device__ float g_ctx[cM*cD];

// ---------------------------------------------------------------------------
// GEMM: out = X @ W^T + bias.  X:[M,K=cD] row-major, W:[N=cD,K=cD] row-major.
// MODE 0: out written head-split [B,H,S,DK];  MODE 1: out written [M,N].
// 128x128x16 tile, 256 threads, 8x8 per thread.
// ---------------------------------------------------------------------------
template<int MODE>
__global__ __launch_bounds__(256) void gemm_nt(
    const float* __restrict__ X, const float* __restrict__ W,
    const float* __restrict__ bias, float* __restrict__ out)
{
    __shared__ float As[16][132];
    __shared__ float Bs[16][132];
    const int tid = threadIdx.x;
    const int m0 = blockIdx.y * 128;
    const int n0 = blockIdx.x * 128;
    const int ty = tid >> 4;         // 0..15
    const int tx = tid & 15;         // 0..15

    float acc[8][8];
    #pragma unroll
    for (int i = 0; i < 8; i++)
        #pragma unroll
        for (int j = 0; j < 8; j++) acc[i][j] = 0.f;

    for (int k0 = 0; k0 < cD; k0 += 16) {
        #pragma unroll
        for (int it = 0; it < 2; it++) {
            int idx = tid + it * 256;        // 0..511
            int row = idx >> 2;              // 0..127
            int c4  = (idx & 3) << 2;        // 0,4,8,12
            float4 xa = *(const float4*)&X[(size_t)(m0 + row) * cD + k0 + c4];
            As[c4+0][row] = xa.x; As[c4+1][row] = xa.y;
            As[c4+2][row] = xa.z; As[c4+3][row] = xa.w;
            float4 wa = *(const float4*)&W[(size_t)(n0 + row) * cD + k0 + c4];
            Bs[c4+0][row] = wa.x; Bs[c4+1][row] = wa.y;
            Bs[c4+2][row] = wa.z; Bs[c4+3][row] = wa.w;
        }
        __syncthreads();
        #pragma unroll
        for (int k = 0; k < 16; k++) {
            float a[8], bb[8];
            *(float4*)&a[0]  = *(const float4*)&As[k][ty*8];
            *(float4*)&a[4]  = *(const float4*)&As[k][ty*8+4];
            *(float4*)&bb[0] = *(const float4*)&Bs[k][tx*8];
            *(float4*)&bb[4] = *(const float4*)&Bs[k][tx*8+4];
            #pragma unroll
            for (int i = 0; i < 8; i++)
                #pragma unroll
                for (int j = 0; j < 8; j++)
                    acc[i][j] += a[i] * bb[j];
        }
        __syncthreads();
    }

    float bv[8];
    #pragma unroll
    for (int j = 0; j < 8; j++) bv[j] = bias[n0 + tx*8 + j];

    #pragma unroll
    for (int i = 0; i < 8; i++) {
        float4 v0 = make_float4(acc[i][0]+bv[0], acc[i][1]+bv[1],
                                acc[i][2]+bv[2], acc[i][3]+bv[3]);
        float4 v1 = make_float4(acc[i][4]+bv[4], acc[i][5]+bv[5],
                                acc[i][6]+bv[6], acc[i][7]+bv[7]);
        int m = m0 + ty*8 + i;
        if (MODE == 1) {
            size_t off = (size_t)m * cD + n0 + tx*8;
            *(float4*)&out[off]   = v0;
            *(float4*)&out[off+4] = v1;
        } else {
            int n  = n0 + tx*8;                 // 8-aligned -> stays in one head
            int h  = n / cDK, d0 = n % cDK;
            int b  = m / cS,  s  = m % cS;
            size_t base = ((size_t)(b*cH + h) * cS + s) * cDK + d0;
            *(float4*)&out[base]   = v0;
            *(float4*)&out[base+4] = v1;
        }
    }
}

// ---------------------------------------------------------------------------
// Flash attention (fp32, online softmax). One CTA per (q-tile of 64, h, b).
// 256 threads as 16x16; each thread owns a 4x4 score tile and 4x4 output tile.
// Smem (dynamic, 69632 B): Qts[k][r], Kts[k][c], Vs[c][d], Ps[r][c], stride 68.
// ---------------------------------------------------------------------------
static constexpr int ATTN_SMEM = 4 * 64 * 68 * 4;   // 69632 bytes

__global__ __launch_bounds__(256) void attn_fused()
{
    extern __shared__ float sm[];
    float* Qts = sm;                 // [64][68]  (k-major)
    float* Kts = sm + 4352;          // [64][68]  (k-major)
    float* Vs  = sm + 2*4352;        // [64][68]  (row = c, col = d)
    float* Ps  = sm + 3*4352;        // [64][68]  (row = r, col = c)

    const int tid = threadIdx.x;
    const int ty  = tid >> 4;        // 0..15 -> score rows ty*4..+3
    const int tx  = tid & 15;        // 0..15 -> score cols / d cols tx*4..+3
    const int q0  = blockIdx.x * 64;
    const int h   = blockIdx.y;
    const int b   = blockIdx.z;

    const size_t head_off = (size_t)(b*cH + h) * cS * cDK;
    const float* Qh = g_q + head_off;
    const float* Kh = g_k + head_off;
    const float* Vh = g_v + head_off;
    const float scale = 0.125f;      // 1/sqrt(64)

    // Load Q tile transposed + pre-scaled
    #pragma unroll
    for (int it = 0; it < 4; it++) {
        int idx = tid + it * 256;    // 0..1023
        int r   = idx >> 4;          // 0..63
        int c4  = (idx & 15) << 2;   // 0..60
        float4 qa = *(const float4*)&Qh[(size_t)(q0 + r) * cDK + c4];
        Qts[(c4+0)*68 + r] = qa.x * scale;
        Qts[(c4+1)*68 + r] = qa.y * scale;
        Qts[(c4+2)*68 + r] = qa.z * scale;
        Qts[(c4+3)*68 + r] = qa.w * scale;
    }

    float o[4][4];
    #pragma unroll
    for (int i = 0; i < 4; i++)
        #pragma unroll
        for (int j = 0; j < 4; j++) o[i][j] = 0.f;
    float mrow[4] = {-1e30f, -1e30f, -1e30f, -1e30f};
    float lrow[4] = {0.f, 0.f, 0.f, 0.f};

    for (int kt = 0; kt < cS / 64; kt++) {
        __syncthreads();             // protect Vs/Ps reuse (and Q on iter 0)
        // Load K (transposed) and V tiles
        #pragma unroll
        for (int it = 0; it < 4; it++) {
            int idx = tid + it * 256;
            int r   = idx >> 4;
            int c4  = (idx & 15) << 2;
            float4 ka = *(const float4*)&Kh[(size_t)(kt*64 + r) * cDK + c4];
            Kts[(c4+0)*68 + r] = ka.x;
            Kts[(c4+1)*68 + r] = ka.y;
            Kts[(c4+2)*68 + r] = ka.z;
            Kts[(c4+3)*68 + r] = ka.w;
            float4 va = *(const float4*)&Vh[(size_t)(kt*64 + r) * cDK + c4];
            *(float4*)&Vs[r*68 + c4] = va;
        }
        __syncthreads();

        // Scores: s[i][j] = sum_k Q[r,k]*K[c,k]  (Q pre-scaled)
        float sv[4][4];
        #pragma unroll
        for (int i = 0; i < 4; i++)
            #pragma unroll
            for (int j = 0; j < 4; j++) sv[i][j] = 0.f;
        #pragma unroll 8
        for (int k = 0; k < cDK; k++) {
            float4 a  = *(const float4*)&Qts[k*68 + ty*4];
            float4 bk = *(const float4*)&Kts[k*68 + tx*4];
            sv[0][0] += a.x*bk.x; sv[0][1] += a.x*bk.y; sv[0][2] += a.x*bk.z; sv[0][3] += a.x*bk.w;
            sv[1][0] += a.y*bk.x; sv[1][1] += a.y*bk.y; sv[1][2] += a.y*bk.z; sv[1][3] += a.y*bk.w;
            sv[2][0] += a.z*bk.x; sv[2][1] += a.z*bk.y; sv[2][2] += a.z*bk.z; sv[2][3] += a.z*bk.w;
            sv[3][0] += a.w*bk.x; sv[3][1] += a.w*bk.y; sv[3][2] += a.w*bk.z; sv[3][3] += a.w*bk.w;
        }

        // Online softmax (row groups span 16 lanes: xor offsets 1,2,4,8)
        #pragma unroll
        for (int i = 0; i < 4; i++) {
            float mx = fmaxf(fmaxf(sv[i][0], sv[i][1]), fmaxf(sv[i][2], sv[i][3]));
            #pragma unroll
            for (int off = 1; off < 16; off <<= 1)
                mx = fmaxf(mx, __shfl_xor_sync(0xffffffffu, mx, off));
            float mnew = fmaxf(mrow[i], mx);
            float corr = __expf(mrow[i] - mnew);
            mrow[i] = mnew;
            float ssum = 0.f;
            #pragma unroll
            for (int j = 0; j < 4; j++) {
                float p = __expf(sv[i][j] - mnew);
                sv[i][j] = p;
                ssum += p;
            }
            #pragma unroll
            for (int off = 1; off < 16; off <<= 1)
                ssum += __shfl_xor_sync(0xffffffffu, ssum, off);
            lrow[i] = lrow[i] * corr + ssum;
            #pragma unroll
            for (int j = 0; j < 4; j++) o[i][j] *= corr;
        }

        // Publish P tile
        #pragma unroll
        for (int i = 0; i < 4; i++)
            *(float4*)&Ps[(ty*4 + i)*68 + tx*4] =
                make_float4(sv[i][0], sv[i][1], sv[i][2], sv[i][3]);
        __syncthreads();

        // o += P @ V
        #pragma unroll 8
        for (int c = 0; c < 64; c++) {
            float a0 = Ps[(ty*4+0)*68 + c];
            float a1 = Ps[(ty*4+1)*68 + c];
            float a2 = Ps[(ty*4+2)*68 + c];
            float a3 = Ps[(ty*4+3)*68 + c];
            float4 vv = *(const float4*)&Vs[c*68 + tx*4];
            o[0][0] += a0*vv.x; o[0][1] += a0*vv.y; o[0][2] += a0*vv.z; o[0][3] += a0*vv.w;
            o[1][0] += a1*vv.x; o[1][1] += a1*vv.y; o[1][2] += a1*vv.z; o[1][3] += a1*vv.w;
            o[2][0] += a2*vv.x; o[2][1] += a2*vv.y; o[2][2] += a2*vv.z; o[2][3] += a2*vv.w;
            o[3][0] += a3*vv.x; o[3][1] += a3*vv.y; o[3][2] += a3*vv.z; o[3][3] += a3*vv.w;
        }
    }

    // Normalize and write ctx in [B,S,D] layout
    #pragma unroll
    for (int i = 0; i < 4; i++) {
        float inv = 1.0f / lrow[i];
        float4 r4 = make_float4(o[i][0]*inv, o[i][1]*inv, o[i][2]*inv, o[i][3]*inv);
        size_t off = ((size_t)(b*cS + q0 + ty*4 + i)) * cD + h*cDK + tx*4;
        *(float4*)&g_ctx[off] = r4;
    }
}

// ---------------------------------------------------------------------------
extern "C" void kernel_launch(void* const* d_in, const int* in_sizes, int n_in,
                              void* d_out, int out_size)
{
    const float* Q  = (const float*)d_in[0];
    const float* K  = (const float*)d_in[1];
    const float* V  = (const float*)d_in[2];
    const float* wq = (const float*)d_in[3];
    const float* bq = (const float*)d_in[4];
    const float* wk = (const float*)d_in[5];
    const float* bk = (const float*)d_in[6];
    const float* wv = (const float*)d_in[7];
    const float* bv = (const float*)d_in[8];
    const float* wo = (const float*)d_in[9];
    const float* bo = (const float*)d_in[10];
    float* out = (float*)d_out;

    float *pq, *pk, *pv, *pctx;
    cudaGetSymbolAddress((void**)&pq,   g_q);
    cudaGetSymbolAddress((void**)&pk,   g_k);
    cudaGetSymbolAddress((void**)&pv,   g_v);
    cudaGetSymbolAddress((void**)&pctx, g_ctx);

    cudaFuncSetAttribute(attn_fused,
                         cudaFuncAttributeMaxDynamicSharedMemorySize, ATTN_SMEM);

    dim3 gg(cD / 128, cM / 128);   // (8, 32)
    gemm_nt<0><<<gg, 256>>>(Q, wq, bq, pq);
    gemm_nt<0><<<gg, 256>>>(K, wk, bk, pk);
    gemm_nt<0><<<gg, 256>>>(V, wv, bv, pv);
    attn_fused<<<dim3(cS/64, cH, cB), 256, ATTN_SMEM>>>();
    gemm_nt<1><<<gg, 256>>>(pctx, wo, bo, out);
}

// round 3
// speedup vs baseline: 1.4057x; 1.4057x over previous
#include <cuda_runtime.h>
#include <cstdint>
#include <math.h>

static constexpr int cB  = 2;
static constexpr int cS  = 2048;
static constexpr int cD  = 1024;
static constexpr int cH  = 16;
static constexpr int cDK = 64;
static constexpr int cM  = cB * cS;   // 4096

// Scratch (allocation-free): q/k/v head-split [B,H,S,DK], ctx [M,D]
__device__ float g_q[cB*cH*cS*cDK];
__device__ float g_k[cB*cH*cS*cDK];
__device__ float g_v[cB*cH*cS*cDK];
__device__ float g_ctx[cM*cD];

__device__ __forceinline__ uint32_t f32_to_tf32(float f) {
    uint32_t u;
    asm("cvt.rna.tf32.f32 %0, %1;" : "=r"(u) : "f"(f));
    return u;
}

// ---------------------------------------------------------------------------
// tf32 mma.sync GEMM: out = X @ W^T + bias.
// X:[M,1024] row-major, W:[1024,1024] row-major (rows = N, K contiguous).
// 128x128 CTA tile, BK=32, 8 warps each 64x32 via m16n8k8, double-buffered.
// MODE 0: out head-split [B,H,S,DK]; MODE 1: out [M,N].
// ---------------------------------------------------------------------------
static constexpr int KSTR   = 36;            // smem row stride (words)
static constexpr int TILE_W = 128 * KSTR;    // words per 128x32 tile
static constexpr int GEMM_SMEM = 2 * 2 * TILE_W * 4;  // 73728 bytes
static constexpr int NCHUNK = cD / 32;       // 32

template<int MODE>
__global__ __launch_bounds__(256) void gemm_mma(
    const float* __restrict__ X, const float* __restrict__ W,
    const float* __restrict__ bias, float* __restrict__ out)
{
    extern __shared__ uint32_t smw[];
    const int tid  = threadIdx.x;
    const int wid  = tid >> 5;
    const int lane = tid & 31;
    const int gid  = lane >> 2;      // 0..7
    const int tig  = lane & 3;       // 0..3
    const int m0 = blockIdx.y * 128;
    const int n0 = blockIdx.x * 128;
    const int wm = (wid & 1) * 64;   // warp m offset in tile
    const int wn = (wid >> 1) * 32;  // warp n offset in tile

    float acc[4][4][4];
    #pragma unroll
    for (int a = 0; a < 4; a++)
        #pragma unroll
        for (int b = 0; b < 4; b++)
            #pragma unroll
            for (int c = 0; c < 4; c++) acc[a][b][c] = 0.f;

    float4 sa[4], sb[4];

    auto ldg_chunk = [&](int kt) {
        const int k0 = kt * 32;
        #pragma unroll
        for (int it = 0; it < 4; it++) {
            int idx = tid + it * 256;        // 0..1023
            int row = idx >> 3;              // 0..127
            int c4  = (idx & 7) << 2;        // 0..28
            sa[it] = *(const float4*)&X[(size_t)(m0 + row) * cD + k0 + c4];
            sb[it] = *(const float4*)&W[(size_t)(n0 + row) * cD + k0 + c4];
        }
    };
    auto sts_chunk = [&](int buf) {
        uint32_t* A = smw + buf * 2 * TILE_W;
        uint32_t* B = A + TILE_W;
        #pragma unroll
        for (int it = 0; it < 4; it++) {
            int idx = tid + it * 256;
            int row = idx >> 3;
            int c4  = (idx & 7) << 2;
            *(uint4*)(A + row * KSTR + c4) =
                make_uint4(f32_to_tf32(sa[it].x), f32_to_tf32(sa[it].y),
                           f32_to_tf32(sa[it].z), f32_to_tf32(sa[it].w));
            *(uint4*)(B + row * KSTR + c4) =
                make_uint4(f32_to_tf32(sb[it].x), f32_to_tf32(sb[it].y),
                           f32_to_tf32(sb[it].z), f32_to_tf32(sb[it].w));
        }
    };
    auto compute = [&](int buf) {
        const uint32_t* A = smw + buf * 2 * TILE_W;
        const uint32_t* B = A + TILE_W;
        #pragma unroll
        for (int ks = 0; ks < 4; ks++) {
            const int kk = ks * 8;
            uint32_t af[4][4], bf[4][2];
            #pragma unroll
            for (int mt = 0; mt < 4; mt++) {
                const uint32_t* p = A + (wm + mt*16 + gid) * KSTR + kk + tig;
                af[mt][0] = p[0];
                af[mt][1] = p[8 * KSTR];
                af[mt][2] = p[4];
                af[mt][3] = p[8 * KSTR + 4];
            }
            #pragma unroll
            for (int nt = 0; nt < 4; nt++) {
                const uint32_t* p = B + (wn + nt*8 + gid) * KSTR + kk + tig;
                bf[nt][0] = p[0];
                bf[nt][1] = p[4];
            }
            #pragma unroll
            for (int mt = 0; mt < 4; mt++)
                #pragma unroll
                for (int nt = 0; nt < 4; nt++)
                    asm volatile(
                        "mma.sync.aligned.m16n8k8.row.col.f32.tf32.tf32.f32 "
                        "{%0,%1,%2,%3}, {%4,%5,%6,%7}, {%8,%9}, {%0,%1,%2,%3};"
                        : "+f"(acc[mt][nt][0]), "+f"(acc[mt][nt][1]),
                          "+f"(acc[mt][nt][2]), "+f"(acc[mt][nt][3])
                        : "r"(af[mt][0]), "r"(af[mt][1]),
                          "r"(af[mt][2]), "r"(af[mt][3]),
                          "r"(bf[nt][0]), "r"(bf[nt][1]));
        }
    };

    ldg_chunk(0);
    sts_chunk(0);
    __syncthreads();
    for (int kt = 0; kt < NCHUNK; kt++) {
        const int buf = kt & 1;
        if (kt + 1 < NCHUNK) ldg_chunk(kt + 1);
        compute(buf);
        if (kt + 1 < NCHUNK) sts_chunk(buf ^ 1);
        __syncthreads();
    }

    // Epilogue: acc[mt][nt]{c0..c3}: rows gid/gid+8, cols 2*tig/2*tig+1
    #pragma unroll
    for (int mt = 0; mt < 4; mt++) {
        #pragma unroll
        for (int i = 0; i < 2; i++) {
            const int m = m0 + wm + mt*16 + gid + i*8;
            const int bb = m / cS, ss = m % cS;
            #pragma unroll
            for (int nt = 0; nt < 4; nt++) {
                const int n = n0 + wn + nt*8 + 2*tig;
                float2 bv = *(const float2*)&bias[n];
                float2 o2 = make_float2(acc[mt][nt][i*2+0] + bv.x,
                                        acc[mt][nt][i*2+1] + bv.y);
                size_t base;
                if (MODE == 1) {
                    base = (size_t)m * cD + n;
                } else {
                    int h = n / cDK, d0 = n % cDK;
                    base = ((size_t)(bb * cH + h) * cS + ss) * cDK + d0;
                }
                *(float2*)&out[base] = o2;
            }
        }
    }
}

// ---------------------------------------------------------------------------
// Flash attention (fp32, online softmax) — unchanged (known good).
// ---------------------------------------------------------------------------
static constexpr int ATTN_SMEM = 4 * 64 * 68 * 4;   // 69632 bytes

__global__ __launch_bounds__(256) void attn_fused()
{
    extern __shared__ float sm[];
    float* Qts = sm;                 // [64][68]  (k-major)
    float* Kts = sm + 4352;          // [64][68]  (k-major)
    float* Vs  = sm + 2*4352;        // [64][68]  (row = c, col = d)
    float* Ps  = sm + 3*4352;        // [64][68]  (row = r, col = c)

    const int tid = threadIdx.x;
    const int ty  = tid >> 4;
    const int tx  = tid & 15;
    const int q0  = blockIdx.x * 64;
    const int h   = blockIdx.y;
    const int b   = blockIdx.z;

    const size_t head_off = (size_t)(b*cH + h) * cS * cDK;
    const float* Qh = g_q + head_off;
    const float* Kh = g_k + head_off;
    const float* Vh = g_v + head_off;
    const float scale = 0.125f;

    #pragma unroll
    for (int it = 0; it < 4; it++) {
        int idx = tid + it * 256;
        int r   = idx >> 4;
        int c4  = (idx & 15) << 2;
        float4 qa = *(const float4*)&Qh[(size_t)(q0 + r) * cDK + c4];
        Qts[(c4+0)*68 + r] = qa.x * scale;
        Qts[(c4+1)*68 + r] = qa.y * scale;
        Qts[(c4+2)*68 + r] = qa.z * scale;
        Qts[(c4+3)*68 + r] = qa.w * scale;
    }

    float o[4][4];
    #pragma unroll
    for (int i = 0; i < 4; i++)
        #pragma unroll
        for (int j = 0; j < 4; j++) o[i][j] = 0.f;
    float mrow[4] = {-1e30f, -1e30f, -1e30f, -1e30f};
    float lrow[4] = {0.f, 0.f, 0.f, 0.f};

    for (int kt = 0; kt < cS / 64; kt++) {
        __syncthreads();
        #pragma unroll
        for (int it = 0; it < 4; it++) {
            int idx = tid + it * 256;
            int r   = idx >> 4;
            int c4  = (idx & 15) << 2;
            float4 ka = *(const float4*)&Kh[(size_t)(kt*64 + r) * cDK + c4];
            Kts[(c4+0)*68 + r] = ka.x;
            Kts[(c4+1)*68 + r] = ka.y;
            Kts[(c4+2)*68 + r] = ka.z;
            Kts[(c4+3)*68 + r] = ka.w;
            float4 va = *(const float4*)&Vh[(size_t)(kt*64 + r) * cDK + c4];
            *(float4*)&Vs[r*68 + c4] = va;
        }
        __syncthreads();

        float sv[4][4];
        #pragma unroll
        for (int i = 0; i < 4; i++)
            #pragma unroll
            for (int j = 0; j < 4; j++) sv[i][j] = 0.f;
        #pragma unroll 8
        for (int k = 0; k < cDK; k++) {
            float4 a  = *(const float4*)&Qts[k*68 + ty*4];
            float4 bk = *(const float4*)&Kts[k*68 + tx*4];
            sv[0][0] += a.x*bk.x; sv[0][1] += a.x*bk.y; sv[0][2] += a.x*bk.z; sv[0][3] += a.x*bk.w;
            sv[1][0] += a.y*bk.x; sv[1][1] += a.y*bk.y; sv[1][2] += a.y*bk.z; sv[1][3] += a.y*bk.w;
            sv[2][0] += a.z*bk.x; sv[2][1] += a.z*bk.y; sv[2][2] += a.z*bk.z; sv[2][3] += a.z*bk.w;
            sv[3][0] += a.w*bk.x; sv[3][1] += a.w*bk.y; sv[3][2] += a.w*bk.z; sv[3][3] += a.w*bk.w;
        }

        #pragma unroll
        for (int i = 0; i < 4; i++) {
            float mx = fmaxf(fmaxf(sv[i][0], sv[i][1]), fmaxf(sv[i][2], sv[i][3]));
            #pragma unroll
            for (int off = 1; off < 16; off <<= 1)
                mx = fmaxf(mx, __shfl_xor_sync(0xffffffffu, mx, off));
            float mnew = fmaxf(mrow[i], mx);
            float corr = __expf(mrow[i] - mnew);
            mrow[i] = mnew;
            float ssum = 0.f;
            #pragma unroll
            for (int j = 0; j < 4; j++) {
                float p = __expf(sv[i][j] - mnew);
                sv[i][j] = p;
                ssum += p;
            }
            #pragma unroll
            for (int off = 1; off < 16; off <<= 1)
                ssum += __shfl_xor_sync(0xffffffffu, ssum, off);
            lrow[i] = lrow[i] * corr + ssum;
            #pragma unroll
            for (int j = 0; j < 4; j++) o[i][j] *= corr;
        }

        #pragma unroll
        for (int i = 0; i < 4; i++)
            *(float4*)&Ps[(ty*4 + i)*68 + tx*4] =
                make_float4(sv[i][0], sv[i][1], sv[i][2], sv[i][3]);
        __syncthreads();

        #pragma unroll 8
        for (int c = 0; c < 64; c++) {
            float a0 = Ps[(ty*4+0)*68 + c];
            float a1 = Ps[(ty*4+1)*68 + c];
            float a2 = Ps[(ty*4+2)*68 + c];
            float a3 = Ps[(ty*4+3)*68 + c];
            float4 vv = *(const float4*)&Vs[c*68 + tx*4];
            o[0][0] += a0*vv.x; o[0][1] += a0*vv.y; o[0][2] += a0*vv.z; o[0][3] += a0*vv.w;
            o[1][0] += a1*vv.x; o[1][1] += a1*vv.y; o[1][2] += a1*vv.z; o[1][3] += a1*vv.w;
            o[2][0] += a2*vv.x; o[2][1] += a2*vv.y; o[2][2] += a2*vv.z; o[2][3] += a2*vv.w;
            o[3][0] += a3*vv.x; o[3][1] += a3*vv.y; o[3][2] += a3*vv.z; o[3][3] += a3*vv.w;
        }
    }

    #pragma unroll
    for (int i = 0; i < 4; i++) {
        float inv = 1.0f / lrow[i];
        float4 r4 = make_float4(o[i][0]*inv, o[i][1]*inv, o[i][2]*inv, o[i][3]*inv);
        size_t off = ((size_t)(b*cS + q0 + ty*4 + i)) * cD + h*cDK + tx*4;
        *(float4*)&g_ctx[off] = r4;
    }
}

// ---------------------------------------------------------------------------
extern "C" void kernel_launch(void* const* d_in, const int* in_sizes, int n_in,
                              void* d_out, int out_size)
{
    const float* Q  = (const float*)d_in[0];
    const float* K  = (const float*)d_in[1];
    const float* V  = (const float*)d_in[2];
    const float* wq = (const float*)d_in[3];
    const float* bq = (const float*)d_in[4];
    const float* wk = (const float*)d_in[5];
    const float* bk = (const float*)d_in[6];
    const float* wv = (const float*)d_in[7];
    const float* bv = (const float*)d_in[8];
    const float* wo = (const float*)d_in[9];
    const float* bo = (const float*)d_in[10];
    float* out = (float*)d_out;

    float *pq, *pk, *pv, *pctx;
    cudaGetSymbolAddress((void**)&pq,   g_q);
    cudaGetSymbolAddress((void**)&pk,   g_k);
    cudaGetSymbolAddress((void**)&pv,   g_v);
    cudaGetSymbolAddress((void**)&pctx, g_ctx);

    cudaFuncSetAttribute(attn_fused,
                         cudaFuncAttributeMaxDynamicSharedMemorySize, ATTN_SMEM);
    cudaFuncSetAttribute(gemm_mma<0>,
                         cudaFuncAttributeMaxDynamicSharedMemorySize, GEMM_SMEM);
    cudaFuncSetAttribute(gemm_mma<1>,
                         cudaFuncAttributeMaxDynamicSharedMemorySize, GEMM_SMEM);

    dim3 gg(cD / 128, cM / 128);   // (8, 32)
    gemm_mma<0><<<gg, 256, GEMM_SMEM>>>(Q, wq, bq, pq);
    gemm_mma<0><<<gg, 256, GEMM_SMEM>>>(K, wk, bk, pk);
    gemm_mma<0><<<gg, 256, GEMM_SMEM>>>(V, wv, bv, pv);
    attn_fused<<<dim3(cS/64, cH, cB), 256, ATTN_SMEM>>>();
    gemm_mma<1><<<gg, 256, GEMM_SMEM>>>(pctx, wo, bo, out);
}

// round 4
// speedup vs baseline: 2.7109x; 1.9285x over previous
#include <cuda_runtime.h>
#include <cstdint>
#include <math.h>

static constexpr int cB  = 2;
static constexpr int cS  = 2048;
static constexpr int cD  = 1024;
static constexpr int cH  = 16;
static constexpr int cDK = 64;
static constexpr int cM  = cB * cS;   // 4096

// Scratch (allocation-free): q/k/v head-split [B,H,S,DK], ctx [M,D]
__device__ float g_q[cB*cH*cS*cDK];
__device__ float g_k[cB*cH*cS*cDK];
__device__ float g_v[cB*cH*cS*cDK];
__device__ float g_ctx[cM*cD];

__device__ __forceinline__ uint32_t f32_to_tf32(float f) {
    uint32_t u;
    asm("cvt.rna.tf32.f32 %0, %1;" : "=r"(u) : "f"(f));
    return u;
}

__device__ __forceinline__ void mma_tf32(
    float* c, uint32_t a0, uint32_t a1, uint32_t a2, uint32_t a3,
    uint32_t b0, uint32_t b1)
{
    asm volatile(
        "mma.sync.aligned.m16n8k8.row.col.f32.tf32.tf32.f32 "
        "{%0,%1,%2,%3}, {%4,%5,%6,%7}, {%8,%9}, {%0,%1,%2,%3};"
        : "+f"(c[0]), "+f"(c[1]), "+f"(c[2]), "+f"(c[3])
        : "r"(a0), "r"(a1), "r"(a2), "r"(a3), "r"(b0), "r"(b1));
}

// ---------------------------------------------------------------------------
// tf32 mma.sync GEMM: out = X @ W^T + bias (unchanged from R3).
// ---------------------------------------------------------------------------
static constexpr int KSTR   = 36;
static constexpr int TILE_W = 128 * KSTR;
static constexpr int GEMM_SMEM = 2 * 2 * TILE_W * 4;  // 73728 bytes
static constexpr int NCHUNK = cD / 32;

template<int MODE>
__global__ __launch_bounds__(256) void gemm_mma(
    const float* __restrict__ X, const float* __restrict__ W,
    const float* __restrict__ bias, float* __restrict__ out)
{
    extern __shared__ uint32_t smw[];
    const int tid  = threadIdx.x;
    const int wid  = tid >> 5;
    const int lane = tid & 31;
    const int gid  = lane >> 2;
    const int tig  = lane & 3;
    const int m0 = blockIdx.y * 128;
    const int n0 = blockIdx.x * 128;
    const int wm = (wid & 1) * 64;
    const int wn = (wid >> 1) * 32;

    float acc[4][4][4];
    #pragma unroll
    for (int a = 0; a < 4; a++)
        #pragma unroll
        for (int b = 0; b < 4; b++)
            #pragma unroll
            for (int c = 0; c < 4; c++) acc[a][b][c] = 0.f;

    float4 sa[4], sb[4];

    auto ldg_chunk = [&](int kt) {
        const int k0 = kt * 32;
        #pragma unroll
        for (int it = 0; it < 4; it++) {
            int idx = tid + it * 256;
            int row = idx >> 3;
            int c4  = (idx & 7) << 2;
            sa[it] = *(const float4*)&X[(size_t)(m0 + row) * cD + k0 + c4];
            sb[it] = *(const float4*)&W[(size_t)(n0 + row) * cD + k0 + c4];
        }
    };
    auto sts_chunk = [&](int buf) {
        uint32_t* A = smw + buf * 2 * TILE_W;
        uint32_t* B = A + TILE_W;
        #pragma unroll
        for (int it = 0; it < 4; it++) {
            int idx = tid + it * 256;
            int row = idx >> 3;
            int c4  = (idx & 7) << 2;
            *(uint4*)(A + row * KSTR + c4) =
                make_uint4(f32_to_tf32(sa[it].x), f32_to_tf32(sa[it].y),
                           f32_to_tf32(sa[it].z), f32_to_tf32(sa[it].w));
            *(uint4*)(B + row * KSTR + c4) =
                make_uint4(f32_to_tf32(sb[it].x), f32_to_tf32(sb[it].y),
                           f32_to_tf32(sb[it].z), f32_to_tf32(sb[it].w));
        }
    };
    auto compute = [&](int buf) {
        const uint32_t* A = smw + buf * 2 * TILE_W;
        const uint32_t* B = A + TILE_W;
        #pragma unroll
        for (int ks = 0; ks < 4; ks++) {
            const int kk = ks * 8;
            uint32_t af[4][4], bf[4][2];
            #pragma unroll
            for (int mt = 0; mt < 4; mt++) {
                const uint32_t* p = A + (wm + mt*16 + gid) * KSTR + kk + tig;
                af[mt][0] = p[0];
                af[mt][1] = p[8 * KSTR];
                af[mt][2] = p[4];
                af[mt][3] = p[8 * KSTR + 4];
            }
            #pragma unroll
            for (int nt = 0; nt < 4; nt++) {
                const uint32_t* p = B + (wn + nt*8 + gid) * KSTR + kk + tig;
                bf[nt][0] = p[0];
                bf[nt][1] = p[4];
            }
            #pragma unroll
            for (int mt = 0; mt < 4; mt++)
                #pragma unroll
                for (int nt = 0; nt < 4; nt++)
                    mma_tf32(acc[mt][nt], af[mt][0], af[mt][1], af[mt][2],
                             af[mt][3], bf[nt][0], bf[nt][1]);
        }
    };

    ldg_chunk(0);
    sts_chunk(0);
    __syncthreads();
    for (int kt = 0; kt < NCHUNK; kt++) {
        const int buf = kt & 1;
        if (kt + 1 < NCHUNK) ldg_chunk(kt + 1);
        compute(buf);
        if (kt + 1 < NCHUNK) sts_chunk(buf ^ 1);
        __syncthreads();
    }

    #pragma unroll
    for (int mt = 0; mt < 4; mt++) {
        #pragma unroll
        for (int i = 0; i < 2; i++) {
            const int m = m0 + wm + mt*16 + gid + i*8;
            const int bb = m / cS, ss = m % cS;
            #pragma unroll
            for (int nt = 0; nt < 4; nt++) {
                const int n = n0 + wn + nt*8 + 2*tig;
                float2 bv = *(const float2*)&bias[n];
                float2 o2 = make_float2(acc[mt][nt][i*2+0] + bv.x,
                                        acc[mt][nt][i*2+1] + bv.y);
                size_t base;
                if (MODE == 1) {
                    base = (size_t)m * cD + n;
                } else {
                    int h = n / cDK, d0 = n % cDK;
                    base = ((size_t)(bb * cH + h) * cS + ss) * cDK + d0;
                }
                *(float2*)&out[base] = o2;
            }
        }
    }
}

// ---------------------------------------------------------------------------
// Flash attention with tf32 mma.sync.
// BM=128 q rows per CTA (8 warps x m16), BN=64 keys per tile, DK=64.
// smem words: Ks[64][68] key-major, Vt[64][68] d-major (V transposed),
//             Ps[128][68] (P tile; also Q staging at start).
// ---------------------------------------------------------------------------
static constexpr int PSTR = 68;
static constexpr int ATTN_SMEM = (64*PSTR + 64*PSTR + 128*PSTR) * 4;  // 69632

__global__ __launch_bounds__(256) void attn_mma()
{
    extern __shared__ uint32_t sw[];
    uint32_t* Ks = sw;                 // [64][68]
    uint32_t* Vt = sw + 64*PSTR;       // [64][68]
    uint32_t* Ps = sw + 128*PSTR;      // [128][68]  (Q staging, then P)

    const int tid  = threadIdx.x;
    const int wid  = tid >> 5;
    const int lane = tid & 31;
    const int gid  = lane >> 2;
    const int tig  = lane & 3;
    const int q0 = blockIdx.x * 128;
    const int h  = blockIdx.y;
    const int b  = blockIdx.z;

    const size_t head_off = (size_t)(b*cH + h) * cS * cDK;
    const float* Qh = g_q + head_off;
    const float* Kh = g_k + head_off;
    const float* Vh = g_v + head_off;

    // Stage Q (scaled by 1/8, exact) as tf32 into Ps region
    #pragma unroll
    for (int it = 0; it < 8; it++) {
        int idx = tid + it * 256;       // 0..2047
        int row = idx >> 4;             // 0..127
        int c4  = (idx & 15) << 2;
        float4 qa = *(const float4*)&Qh[(size_t)(q0 + row) * cDK + c4];
        *(uint4*)&Ps[row*PSTR + c4] =
            make_uint4(f32_to_tf32(qa.x * 0.125f), f32_to_tf32(qa.y * 0.125f),
                       f32_to_tf32(qa.z * 0.125f), f32_to_tf32(qa.w * 0.125f));
    }
    __syncthreads();

    // Q A-frags: warp rows r0 = wid*16+gid, r0+8; 8 k-steps
    const int r0 = wid * 16 + gid;
    uint32_t qf[8][4];
    #pragma unroll
    for (int s = 0; s < 8; s++) {
        const uint32_t* p = Ps + r0 * PSTR + s * 8 + tig;
        qf[s][0] = p[0];
        qf[s][1] = p[8 * PSTR];
        qf[s][2] = p[4];
        qf[s][3] = p[8 * PSTR + 4];
    }

    float o[8][4];
    #pragma unroll
    for (int nt = 0; nt < 8; nt++)
        #pragma unroll
        for (int c = 0; c < 4; c++) o[nt][c] = 0.f;
    float mr0 = -1e30f, mr1 = -1e30f, l0 = 0.f, l1 = 0.f;

    float4 ka[4], va[4];
    auto ldgKV = [&](int kt) {
        const float* Kp = Kh + (size_t)kt * 64 * cDK;
        const float* Vp = Vh + (size_t)kt * 64 * cDK;
        #pragma unroll
        for (int it = 0; it < 4; it++) {
            int idx = tid + it * 256;   // 0..1023
            int row = idx >> 4;         // 0..63
            int c4  = (idx & 15) << 2;
            ka[it] = *(const float4*)&Kp[row * cDK + c4];
            va[it] = *(const float4*)&Vp[row * cDK + c4];
        }
    };

    ldgKV(0);

    for (int kt = 0; kt < cS / 64; kt++) {
        __syncthreads();   // prior readers of Ks/Vt done
        #pragma unroll
        for (int it = 0; it < 4; it++) {
            int idx = tid + it * 256;
            int row = idx >> 4;
            int c4  = (idx & 15) << 2;
            *(uint4*)&Ks[row*PSTR + c4] =
                make_uint4(f32_to_tf32(ka[it].x), f32_to_tf32(ka[it].y),
                           f32_to_tf32(ka[it].z), f32_to_tf32(ka[it].w));
            Vt[(c4+0)*PSTR + row] = f32_to_tf32(va[it].x);
            Vt[(c4+1)*PSTR + row] = f32_to_tf32(va[it].y);
            Vt[(c4+2)*PSTR + row] = f32_to_tf32(va[it].z);
            Vt[(c4+3)*PSTR + row] = f32_to_tf32(va[it].w);
        }
        __syncthreads();
        if (kt + 1 < cS / 64) ldgKV(kt + 1);

        // Scores: 8 n-tiles (keys), 8 k-steps (dk)
        float sc[8][4];
        #pragma unroll
        for (int nt = 0; nt < 8; nt++)
            #pragma unroll
            for (int c = 0; c < 4; c++) sc[nt][c] = 0.f;
        #pragma unroll
        for (int s = 0; s < 8; s++) {
            #pragma unroll
            for (int nt = 0; nt < 8; nt++) {
                const uint32_t* p = Ks + (nt*8 + gid) * PSTR + s * 8 + tig;
                mma_tf32(sc[nt], qf[s][0], qf[s][1], qf[s][2], qf[s][3],
                         p[0], p[4]);
            }
        }

        // Online softmax: rows r0 (c0,c1), r0+8 (c2,c3)
        float mx0 = -1e30f, mx1 = -1e30f;
        #pragma unroll
        for (int nt = 0; nt < 8; nt++) {
            mx0 = fmaxf(mx0, fmaxf(sc[nt][0], sc[nt][1]));
            mx1 = fmaxf(mx1, fmaxf(sc[nt][2], sc[nt][3]));
        }
        #pragma unroll
        for (int off = 1; off < 4; off <<= 1) {
            mx0 = fmaxf(mx0, __shfl_xor_sync(0xffffffffu, mx0, off));
            mx1 = fmaxf(mx1, __shfl_xor_sync(0xffffffffu, mx1, off));
        }
        float mn0 = fmaxf(mr0, mx0);
        float mn1 = fmaxf(mr1, mx1);
        float cor0 = __expf(mr0 - mn0);
        float cor1 = __expf(mr1 - mn1);
        mr0 = mn0; mr1 = mn1;

        float s0 = 0.f, s1 = 0.f;
        #pragma unroll
        for (int nt = 0; nt < 8; nt++) {
            float p00 = __expf(sc[nt][0] - mn0);
            float p01 = __expf(sc[nt][1] - mn0);
            float p10 = __expf(sc[nt][2] - mn1);
            float p11 = __expf(sc[nt][3] - mn1);
            s0 += p00 + p01;
            s1 += p10 + p11;
            *(uint2*)&Ps[r0*PSTR + nt*8 + 2*tig] =
                make_uint2(f32_to_tf32(p00), f32_to_tf32(p01));
            *(uint2*)&Ps[(r0+8)*PSTR + nt*8 + 2*tig] =
                make_uint2(f32_to_tf32(p10), f32_to_tf32(p11));
        }
        #pragma unroll
        for (int off = 1; off < 4; off <<= 1) {
            s0 += __shfl_xor_sync(0xffffffffu, s0, off);
            s1 += __shfl_xor_sync(0xffffffffu, s1, off);
        }
        l0 = l0 * cor0 + s0;
        l1 = l1 * cor1 + s1;
        #pragma unroll
        for (int nt = 0; nt < 8; nt++) {
            o[nt][0] *= cor0; o[nt][1] *= cor0;
            o[nt][2] *= cor1; o[nt][3] *= cor1;
        }

        __syncwarp();   // P stores visible to warp before PV frag loads

        // PV: o += P @ V  (A from Ps rows r0/r0+8, B from Vt)
        #pragma unroll
        for (int s = 0; s < 8; s++) {
            const uint32_t* ap = Ps + r0 * PSTR + s * 8 + tig;
            uint32_t a0 = ap[0];
            uint32_t a1 = ap[8 * PSTR];
            uint32_t a2 = ap[4];
            uint32_t a3 = ap[8 * PSTR + 4];
            #pragma unroll
            for (int nt = 0; nt < 8; nt++) {
                const uint32_t* bp = Vt + (nt*8 + gid) * PSTR + s * 8 + tig;
                mma_tf32(o[nt], a0, a1, a2, a3, bp[0], bp[4]);
            }
        }
        __syncwarp();   // PV reads done before next-iteration P stores
    }

    // Epilogue: normalize and write ctx [B,S,D]
    const float inv0 = 1.0f / l0;
    const float inv1 = 1.0f / l1;
    const size_t row0 = (size_t)(b * cS + q0 + r0) * cD + h * cDK;
    const size_t row1 = row0 + 8 * cD;
    #pragma unroll
    for (int nt = 0; nt < 8; nt++) {
        const int d = nt * 8 + 2 * tig;
        *(float2*)&g_ctx[row0 + d] = make_float2(o[nt][0]*inv0, o[nt][1]*inv0);
        *(float2*)&g_ctx[row1 + d] = make_float2(o[nt][2]*inv1, o[nt][3]*inv1);
    }
}

// ---------------------------------------------------------------------------
extern "C" void kernel_launch(void* const* d_in, const int* in_sizes, int n_in,
                              void* d_out, int out_size)
{
    const float* Q  = (const float*)d_in[0];
    const float* K  = (const float*)d_in[1];
    const float* V  = (const float*)d_in[2];
    const float* wq = (const float*)d_in[3];
    const float* bq = (const float*)d_in[4];
    const float* wk = (const float*)d_in[5];
    const float* bk = (const float*)d_in[6];
    const float* wv = (const float*)d_in[7];
    const float* bv = (const float*)d_in[8];
    const float* wo = (const float*)d_in[9];
    const float* bo = (const float*)d_in[10];
    float* out = (float*)d_out;

    float *pq, *pk, *pv, *pctx;
    cudaGetSymbolAddress((void**)&pq,   g_q);
    cudaGetSymbolAddress((void**)&pk,   g_k);
    cudaGetSymbolAddress((void**)&pv,   g_v);
    cudaGetSymbolAddress((void**)&pctx, g_ctx);

    cudaFuncSetAttribute(attn_mma,
                         cudaFuncAttributeMaxDynamicSharedMemorySize, ATTN_SMEM);
    cudaFuncSetAttribute(gemm_mma<0>,
                         cudaFuncAttributeMaxDynamicSharedMemorySize, GEMM_SMEM);
    cudaFuncSetAttribute(gemm_mma<1>,
                         cudaFuncAttributeMaxDynamicSharedMemorySize, GEMM_SMEM);

    dim3 gg(cD / 128, cM / 128);   // (8, 32)
    gemm_mma<0><<<gg, 256, GEMM_SMEM>>>(Q, wq, bq, pq);
    gemm_mma<0><<<gg, 256, GEMM_SMEM>>>(K, wk, bk, pk);
    gemm_mma<0><<<gg, 256, GEMM_SMEM>>>(V, wv, bv, pv);
    attn_mma<<<dim3(cS/128, cH, cB), 256, ATTN_SMEM>>>();
    gemm_mma<1><<<gg, 256, GEMM_SMEM>>>(pctx, wo, bo, out);
}

// round 5
// speedup vs baseline: 5.5133x; 2.0338x over previous
#include <cuda_runtime.h>
#include <cuda_fp16.h>
#include <cstdint>

static constexpr int cB  = 2;
static constexpr int cS  = 2048;
static constexpr int cD  = 1024;
static constexpr int cH  = 16;
static constexpr int cDK = 64;
static constexpr int cM  = cB * cS;   // 4096

// Scratch (allocation-free): q/k/v head-split [B,H,S,DK] fp16, ctx [M,D] fp16
__device__ __half g_qh[cB*cH*cS*cDK];
__device__ __half g_kh[cB*cH*cS*cDK];
__device__ __half g_vh[cB*cH*cS*cDK];
__device__ __half g_ctxh[cM*cD];

// ---------------------------------------------------------------------------
// Helpers
// ---------------------------------------------------------------------------
__device__ __forceinline__ uint32_t smem_u32(const void* p) {
    uint32_t a;
    asm("{ .reg .u64 t; cvta.to.shared.u64 t, %1; cvt.u32.u64 %0, t; }"
        : "=r"(a) : "l"(p));
    return a;
}
__device__ __forceinline__ uint32_t packh2(float lo, float hi) {
    __half2 h = __floats2half2_rn(lo, hi);
    return *reinterpret_cast<uint32_t*>(&h);
}
__device__ __forceinline__ void ldsm4(uint32_t& r0, uint32_t& r1,
                                      uint32_t& r2, uint32_t& r3, uint32_t a) {
    asm volatile("ldmatrix.sync.aligned.m8n8.x4.shared.b16 {%0,%1,%2,%3}, [%4];"
        : "=r"(r0), "=r"(r1), "=r"(r2), "=r"(r3) : "r"(a));
}
__device__ __forceinline__ void ldsm4t(uint32_t& r0, uint32_t& r1,
                                       uint32_t& r2, uint32_t& r3, uint32_t a) {
    asm volatile("ldmatrix.sync.aligned.m8n8.x4.trans.shared.b16 {%0,%1,%2,%3}, [%4];"
        : "=r"(r0), "=r"(r1), "=r"(r2), "=r"(r3) : "r"(a));
}
__device__ __forceinline__ void mma_f16(
    float* c, uint32_t a0, uint32_t a1, uint32_t a2, uint32_t a3,
    uint32_t b0, uint32_t b1)
{
    asm volatile(
        "mma.sync.aligned.m16n8k16.row.col.f32.f16.f16.f32 "
        "{%0,%1,%2,%3}, {%4,%5,%6,%7}, {%8,%9}, {%0,%1,%2,%3};"
        : "+f"(c[0]), "+f"(c[1]), "+f"(c[2]), "+f"(c[3])
        : "r"(a0), "r"(a1), "r"(a2), "r"(a3), "r"(b0), "r"(b1));
}
__device__ __forceinline__ void cp16(uint32_t dst, const void* src) {
    asm volatile("cp.async.ca.shared.global [%0], [%1], 16;"
        :: "r"(dst), "l"(src));
}
#define CP_COMMIT() asm volatile("cp.async.commit_group;" ::: "memory")
#define CP_WAIT(n)  asm volatile("cp.async.wait_group %0;" :: "n"(n) : "memory")

static constexpr int SH = 72;   // smem stride in halves (144B: +1 16B group/row)

// ---------------------------------------------------------------------------
// fp16 mma GEMM: out = (X @ W^T + bias) * oscale.
// X:[M,1024] (float or half) row-major, W:[1024,1024] float row-major.
// 128x128 CTA tile, BK=64, 8 warps each 64x32 via m16n8k16 + ldmatrix.
// MODE 0: out half, head-split [B,H,S,DK]; MODE 1: out float [M,N].
// ---------------------------------------------------------------------------
static constexpr int GTILE = 128 * SH;                 // halves per tile
static constexpr int GEMM_SMEM = 2 * 2 * GTILE * 2;    // 73728 bytes
static constexpr int GNCH = cD / 64;                   // 16 chunks

template<typename TA, int MODE>
__global__ __launch_bounds__(256) void gemm_h(
    const TA* __restrict__ X, const float* __restrict__ W,
    const float* __restrict__ bias, void* __restrict__ outp, float oscale)
{
    constexpr bool AF32 = (sizeof(TA) == 4);
    extern __shared__ __half smh[];
    const uint32_t smb = smem_u32(smh);
    const int tid  = threadIdx.x;
    const int wid  = tid >> 5;
    const int lane = tid & 31;
    const int gid  = lane >> 2;
    const int tig  = lane & 3;
    const int m0 = blockIdx.y * 128;
    const int n0 = blockIdx.x * 128;
    const int wm = (wid & 1) * 64;
    const int wn = (wid >> 1) * 32;

    float acc[4][4][4];
    #pragma unroll
    for (int a = 0; a < 4; a++)
        #pragma unroll
        for (int b = 0; b < 4; b++)
            #pragma unroll
            for (int c = 0; c < 4; c++) acc[a][b][c] = 0.f;

    float4 sa[8], sb[8];
    uint4  sah[4];

    auto ldg = [&](int kt) {
        const int k0 = kt * 64;
        #pragma unroll
        for (int it = 0; it < 4; it++) {
            int idx = tid + it * 256, row = idx >> 3, c8 = (idx & 7) * 8;
            if constexpr (AF32) {
                const float* xp = (const float*)X + (size_t)(m0 + row) * cD + k0 + c8;
                sa[2*it]   = *(const float4*)xp;
                sa[2*it+1] = *(const float4*)(xp + 4);
            } else {
                sah[it] = *(const uint4*)((const __half*)X +
                            (size_t)(m0 + row) * cD + k0 + c8);
            }
            const float* wp = W + (size_t)(n0 + row) * cD + k0 + c8;
            sb[2*it]   = *(const float4*)wp;
            sb[2*it+1] = *(const float4*)(wp + 4);
        }
    };
    auto sts = [&](int buf) {
        __half* A  = smh + buf * 2 * GTILE;
        __half* Bm = A + GTILE;
        #pragma unroll
        for (int it = 0; it < 4; it++) {
            int idx = tid + it * 256, row = idx >> 3, c8 = (idx & 7) * 8;
            uint4 av;
            if constexpr (AF32)
                av = make_uint4(packh2(sa[2*it].x,   sa[2*it].y),
                                packh2(sa[2*it].z,   sa[2*it].w),
                                packh2(sa[2*it+1].x, sa[2*it+1].y),
                                packh2(sa[2*it+1].z, sa[2*it+1].w));
            else av = sah[it];
            *(uint4*)&A[row * SH + c8] = av;
            *(uint4*)&Bm[row * SH + c8] =
                make_uint4(packh2(sb[2*it].x,   sb[2*it].y),
                           packh2(sb[2*it].z,   sb[2*it].w),
                           packh2(sb[2*it+1].x, sb[2*it+1].y),
                           packh2(sb[2*it+1].z, sb[2*it+1].w));
        }
    };
    auto comp = [&](int buf) {
        const uint32_t Ab = smb + (uint32_t)(buf * 2 * GTILE) * 2;
        const uint32_t Bb = Ab + GTILE * 2;
        #pragma unroll
        for (int ks = 0; ks < 4; ks++) {
            const int kk = ks * 16;
            uint32_t af[4][4], bf[4][2];
            #pragma unroll
            for (int mt = 0; mt < 4; mt++) {
                uint32_t a = Ab + (uint32_t)(((wm + mt*16 + (lane & 15)) * SH
                                 + kk + (lane >> 4) * 8) * 2);
                ldsm4(af[mt][0], af[mt][1], af[mt][2], af[mt][3], a);
            }
            #pragma unroll
            for (int g = 0; g < 2; g++) {
                uint32_t a = Bb + (uint32_t)(((wn + g*16 + ((lane >> 4) & 1) * 8
                                 + (lane & 7)) * SH + kk + ((lane >> 3) & 1) * 8) * 2);
                ldsm4(bf[2*g][0], bf[2*g][1], bf[2*g+1][0], bf[2*g+1][1], a);
            }
            #pragma unroll
            for (int mt = 0; mt < 4; mt++)
                #pragma unroll
                for (int nt = 0; nt < 4; nt++)
                    mma_f16(acc[mt][nt], af[mt][0], af[mt][1], af[mt][2],
                            af[mt][3], bf[nt][0], bf[nt][1]);
        }
    };

    ldg(0); sts(0); __syncthreads();
    for (int kt = 0; kt < GNCH; kt++) {
        const int buf = kt & 1;
        if (kt + 1 < GNCH) ldg(kt + 1);
        comp(buf);
        if (kt + 1 < GNCH) sts(buf ^ 1);
        __syncthreads();
    }

    #pragma unroll
    for (int mt = 0; mt < 4; mt++) {
        #pragma unroll
        for (int i = 0; i < 2; i++) {
            const int m = m0 + wm + mt*16 + gid + i*8;
            const int bb = m / cS, ss = m % cS;
            #pragma unroll
            for (int nt = 0; nt < 4; nt++) {
                const int n = n0 + wn + nt*8 + 2*tig;
                float2 bv = *(const float2*)&bias[n];
                float v0 = (acc[mt][nt][i*2+0] + bv.x) * oscale;
                float v1 = (acc[mt][nt][i*2+1] + bv.y) * oscale;
                if (MODE == 1) {
                    float* o = (float*)outp;
                    *(float2*)&o[(size_t)m * cD + n] = make_float2(v0, v1);
                } else {
                    __half* o = (__half*)outp;
                    int hh = n / cDK, d0 = n % cDK;
                    size_t base = ((size_t)(bb * cH + hh) * cS + ss) * cDK + d0;
                    *(uint32_t*)&o[base] = packh2(v0, v1);
                }
            }
        }
    }
}

// ---------------------------------------------------------------------------
// fp16 flash attention. BM=128 (8 warps x m16), BN=64 keys, DK=64.
// Q/K/V fp16 from gmem; KV via cp.async double-buffer; P register-resident.
// smem halves: Qs[128][72] | K0[64][72] V0[64][72] | K1[64][72] V1[64][72]
// ---------------------------------------------------------------------------
static constexpr int QSH = 128 * SH;     // 9216 halves
static constexpr int KVH = 64 * SH;      // 4608 halves
static constexpr int ATTN_SMEM = (QSH + 4 * KVH) * 2;   // 55296 bytes
static constexpr int NT = cS / 64;       // 32 tiles

__global__ __launch_bounds__(256, 2) void attn_h()
{
    extern __shared__ __half sh[];
    const uint32_t smb = smem_u32(sh);
    const int tid  = threadIdx.x;
    const int wid  = tid >> 5;
    const int lane = tid & 31;
    const int gid  = lane >> 2;
    const int tig  = lane & 3;
    const int q0 = blockIdx.x * 128;
    const int h  = blockIdx.y;
    const int b  = blockIdx.z;

    const size_t head_off = (size_t)(b * cH + h) * cS * cDK;
    const __half* Qh = g_qh + head_off;
    const __half* Kh = g_kh + head_off;
    const __half* Vh = g_vh + head_off;

    // Stage Q (already scaled by 1/8 at projection) into Qs
    #pragma unroll
    for (int it = 0; it < 4; it++) {
        int idx = tid + it * 256, row = idx >> 3, c8 = (idx & 7) * 8;
        *(uint4*)&sh[row * SH + c8] =
            *(const uint4*)&Qh[(size_t)(q0 + row) * cDK + c8];
    }
    __syncthreads();

    // Extract Q A-frags (warp rows wid*16 .. +15), 4 k16-steps
    uint32_t qf[4][4];
    #pragma unroll
    for (int s = 0; s < 4; s++) {
        uint32_t a = smb + (uint32_t)(((wid*16 + (lane & 15)) * SH
                         + s*16 + (lane >> 4) * 8) * 2);
        ldsm4(qf[s][0], qf[s][1], qf[s][2], qf[s][3], a);
    }

    float o[8][4];
    #pragma unroll
    for (int nt = 0; nt < 8; nt++)
        #pragma unroll
        for (int c = 0; c < 4; c++) o[nt][c] = 0.f;
    float mr0 = -1e30f, mr1 = -1e30f, l0 = 0.f, l1 = 0.f;
    const int r0 = wid * 16 + gid;

    auto cp_tile = [&](int kt, int buf) {
        const __half* Kp = Kh + (size_t)kt * 64 * cDK;
        const __half* Vp = Vh + (size_t)kt * 64 * cDK;
        const uint32_t Kb = smb + (uint32_t)(QSH + buf * 2 * KVH) * 2;
        const uint32_t Vb = Kb + KVH * 2;
        #pragma unroll
        for (int it = 0; it < 2; it++) {
            int idx = tid + it * 256, row = idx >> 3, c8 = (idx & 7) * 8;
            uint32_t soff = (uint32_t)((row * SH + c8) * 2);
            cp16(Kb + soff, Kp + (size_t)row * cDK + c8);
            cp16(Vb + soff, Vp + (size_t)row * cDK + c8);
        }
    };

    cp_tile(0, 0);
    CP_COMMIT();

    for (int kt = 0; kt < NT; kt++) {
        const int buf = kt & 1;
        if (kt + 1 < NT) {
            cp_tile(kt + 1, buf ^ 1);
            CP_COMMIT();
            CP_WAIT(1);
        } else {
            CP_WAIT(0);
        }
        __syncthreads();

        const uint32_t Kb = smb + (uint32_t)(QSH + buf * 2 * KVH) * 2;
        const uint32_t Vb = Kb + KVH * 2;

        // Scores: 8 key n-tiles x 4 k16-steps
        float sc[8][4];
        #pragma unroll
        for (int nt = 0; nt < 8; nt++)
            #pragma unroll
            for (int c = 0; c < 4; c++) sc[nt][c] = 0.f;
        #pragma unroll
        for (int s = 0; s < 4; s++) {
            const int kk = s * 16;
            #pragma unroll
            for (int g = 0; g < 4; g++) {
                uint32_t a = Kb + (uint32_t)(((g*16 + ((lane >> 4) & 1) * 8
                                 + (lane & 7)) * SH + kk + ((lane >> 3) & 1) * 8) * 2);
                uint32_t b0, b1, b2, b3;
                ldsm4(b0, b1, b2, b3, a);
                mma_f16(sc[2*g],   qf[s][0], qf[s][1], qf[s][2], qf[s][3], b0, b1);
                mma_f16(sc[2*g+1], qf[s][0], qf[s][1], qf[s][2], qf[s][3], b2, b3);
            }
        }

        // Online softmax (rows r0, r0+8; quad tig 0..3 owns the row)
        float mx0 = -1e30f, mx1 = -1e30f;
        #pragma unroll
        for (int nt = 0; nt < 8; nt++) {
            mx0 = fmaxf(mx0, fmaxf(sc[nt][0], sc[nt][1]));
            mx1 = fmaxf(mx1, fmaxf(sc[nt][2], sc[nt][3]));
        }
        #pragma unroll
        for (int off = 1; off < 4; off <<= 1) {
            mx0 = fmaxf(mx0, __shfl_xor_sync(0xffffffffu, mx0, off));
            mx1 = fmaxf(mx1, __shfl_xor_sync(0xffffffffu, mx1, off));
        }
        const float mn0 = fmaxf(mr0, mx0);
        const float mn1 = fmaxf(mr1, mx1);
        const float cor0 = __expf(mr0 - mn0);
        const float cor1 = __expf(mr1 - mn1);
        mr0 = mn0; mr1 = mn1;

        float s0 = 0.f, s1 = 0.f;
        #pragma unroll
        for (int nt = 0; nt < 8; nt++) {
            sc[nt][0] = __expf(sc[nt][0] - mn0);
            sc[nt][1] = __expf(sc[nt][1] - mn0);
            sc[nt][2] = __expf(sc[nt][2] - mn1);
            sc[nt][3] = __expf(sc[nt][3] - mn1);
            s0 += sc[nt][0] + sc[nt][1];
            s1 += sc[nt][2] + sc[nt][3];
        }
        #pragma unroll
        for (int off = 1; off < 4; off <<= 1) {
            s0 += __shfl_xor_sync(0xffffffffu, s0, off);
            s1 += __shfl_xor_sync(0xffffffffu, s1, off);
        }
        l0 = l0 * cor0 + s0;
        l1 = l1 * cor1 + s1;
        #pragma unroll
        for (int nt = 0; nt < 8; nt++) {
            o[nt][0] *= cor0; o[nt][1] *= cor0;
            o[nt][2] *= cor1; o[nt][3] *= cor1;
        }

        // P -> A-frags directly in registers (C-frag layout == A-frag halves)
        uint32_t pa[4][4];
        #pragma unroll
        for (int s = 0; s < 4; s++) {
            pa[s][0] = packh2(sc[2*s][0],   sc[2*s][1]);
            pa[s][1] = packh2(sc[2*s][2],   sc[2*s][3]);
            pa[s][2] = packh2(sc[2*s+1][0], sc[2*s+1][1]);
            pa[s][3] = packh2(sc[2*s+1][2], sc[2*s+1][3]);
        }

        // PV: o += P @ V, V^T frags via trans ldmatrix (keys = k)
        #pragma unroll
        for (int s = 0; s < 4; s++) {
            #pragma unroll
            for (int g = 0; g < 4; g++) {
                uint32_t a = Vb + (uint32_t)(((s*16 + ((lane >> 3) & 1) * 8
                                 + (lane & 7)) * SH + g*16 + (lane >> 4) * 8) * 2);
                uint32_t b0, b1, b2, b3;
                ldsm4t(b0, b1, b2, b3, a);
                mma_f16(o[2*g],   pa[s][0], pa[s][1], pa[s][2], pa[s][3], b0, b1);
                mma_f16(o[2*g+1], pa[s][0], pa[s][1], pa[s][2], pa[s][3], b2, b3);
            }
        }
        __syncthreads();
    }

    // Epilogue: normalize, write ctx fp16 [B,S,D]
    const float inv0 = 1.0f / l0;
    const float inv1 = 1.0f / l1;
    const size_t row0 = (size_t)(b * cS + q0 + r0) * cD + h * cDK;
    const size_t row1 = row0 + 8 * cD;
    #pragma unroll
    for (int nt = 0; nt < 8; nt++) {
        const int d = nt * 8 + 2 * tig;
        *(uint32_t*)&g_ctxh[row0 + d] = packh2(o[nt][0]*inv0, o[nt][1]*inv0);
        *(uint32_t*)&g_ctxh[row1 + d] = packh2(o[nt][2]*inv1, o[nt][3]*inv1);
    }
}

// ---------------------------------------------------------------------------
extern "C" void kernel_launch(void* const* d_in, const int* in_sizes, int n_in,
                              void* d_out, int out_size)
{
    const float* Q  = (const float*)d_in[0];
    const float* K  = (const float*)d_in[1];
    const float* V  = (const float*)d_in[2];
    const float* wq = (const float*)d_in[3];
    const float* bq = (const float*)d_in[4];
    const float* wk = (const float*)d_in[5];
    const float* bk = (const float*)d_in[6];
    const float* wv = (const float*)d_in[7];
    const float* bv = (const float*)d_in[8];
    const float* wo = (const float*)d_in[9];
    const float* bo = (const float*)d_in[10];
    float* out = (float*)d_out;

    __half *pq, *pk, *pv, *pctx;
    cudaGetSymbolAddress((void**)&pq,   g_qh);
    cudaGetSymbolAddress((void**)&pk,   g_kh);
    cudaGetSymbolAddress((void**)&pv,   g_vh);
    cudaGetSymbolAddress((void**)&pctx, g_ctxh);

    cudaFuncSetAttribute(attn_h,
                         cudaFuncAttributeMaxDynamicSharedMemorySize, ATTN_SMEM);
    cudaFuncSetAttribute((const void*)gemm_h<float, 0>,
                         cudaFuncAttributeMaxDynamicSharedMemorySize, GEMM_SMEM);
    cudaFuncSetAttribute((const void*)gemm_h<__half, 1>,
                         cudaFuncAttributeMaxDynamicSharedMemorySize, GEMM_SMEM);

    dim3 gg(cD / 128, cM / 128);   // (8, 32)
    // Q projection pre-scales by 1/sqrt(DK)=0.125 (exact power of 2)
    gemm_h<float, 0><<<gg, 256, GEMM_SMEM>>>(Q, wq, bq, pq, 0.125f);
    gemm_h<float, 0><<<gg, 256, GEMM_SMEM>>>(K, wk, bk, pk, 1.0f);
    gemm_h<float, 0><<<gg, 256, GEMM_SMEM>>>(V, wv, bv, pv, 1.0f);
    attn_h<<<dim3(cS/128, cH, cB), 256, ATTN_SMEM>>>();
    gemm_h<__half, 1><<<gg, 256, GEMM_SMEM>>>(pctx, wo, bo, out, 1.0f);
}

// round 6
// speedup vs baseline: 6.5667x; 1.1911x over previous
#include <cuda_runtime.h>
#include <cuda_fp16.h>
#include <cstdint>

static constexpr int cB  = 2;
static constexpr int cS  = 2048;
static constexpr int cD  = 1024;
static constexpr int cH  = 16;
static constexpr int cDK = 64;
static constexpr int cM  = cB * cS;   // 4096

// Scratch (allocation-free)
__device__ __half g_qh[cB*cH*cS*cDK];     // q head-split, pre-scaled
__device__ __half g_kh[cB*cH*cS*cDK];
__device__ __half g_vh[cB*cH*cS*cDK];
__device__ __half g_ctxh[cM*cD];          // attention output [M,D]
__device__ __half g_xq[cM*cD];            // fp16 copies of inputs
__device__ __half g_xk[cM*cD];
__device__ __half g_xv[cM*cD];
__device__ __half g_wq[cD*cD];            // fp16 copies of weights
__device__ __half g_wk[cD*cD];
__device__ __half g_wv[cD*cD];
__device__ __half g_wo[cD*cD];

// ---------------------------------------------------------------------------
// Helpers
// ---------------------------------------------------------------------------
__device__ __forceinline__ uint32_t smem_u32(const void* p) {
    uint32_t a;
    asm("{ .reg .u64 t; cvta.to.shared.u64 t, %1; cvt.u32.u64 %0, t; }"
        : "=r"(a) : "l"(p));
    return a;
}
__device__ __forceinline__ uint32_t packh2(float lo, float hi) {
    __half2 h = __floats2half2_rn(lo, hi);
    return *reinterpret_cast<uint32_t*>(&h);
}
__device__ __forceinline__ void ldsm4(uint32_t& r0, uint32_t& r1,
                                      uint32_t& r2, uint32_t& r3, uint32_t a) {
    asm volatile("ldmatrix.sync.aligned.m8n8.x4.shared.b16 {%0,%1,%2,%3}, [%4];"
        : "=r"(r0), "=r"(r1), "=r"(r2), "=r"(r3) : "r"(a));
}
__device__ __forceinline__ void ldsm4t(uint32_t& r0, uint32_t& r1,
                                       uint32_t& r2, uint32_t& r3, uint32_t a) {
    asm volatile("ldmatrix.sync.aligned.m8n8.x4.trans.shared.b16 {%0,%1,%2,%3}, [%4];"
        : "=r"(r0), "=r"(r1), "=r"(r2), "=r"(r3) : "r"(a));
}
__device__ __forceinline__ void mma_f16(
    float* c, uint32_t a0, uint32_t a1, uint32_t a2, uint32_t a3,
    uint32_t b0, uint32_t b1)
{
    asm volatile(
        "mma.sync.aligned.m16n8k16.row.col.f32.f16.f16.f32 "
        "{%0,%1,%2,%3}, {%4,%5,%6,%7}, {%8,%9}, {%0,%1,%2,%3};"
        : "+f"(c[0]), "+f"(c[1]), "+f"(c[2]), "+f"(c[3])
        : "r"(a0), "r"(a1), "r"(a2), "r"(a3), "r"(b0), "r"(b1));
}
__device__ __forceinline__ void cp16(uint32_t dst, const void* src) {
    asm volatile("cp.async.ca.shared.global [%0], [%1], 16;"
        :: "r"(dst), "l"(src));
}
#define CP_COMMIT() asm volatile("cp.async.commit_group;" ::: "memory")
#define CP_WAIT(n)  asm volatile("cp.async.wait_group %0;" :: "n"(n) : "memory")

static constexpr int SH = 72;   // smem stride in halves per 64-half row

// ---------------------------------------------------------------------------
// fp32 -> fp16 bulk convert (bandwidth-bound, ~15us total for all launches)
// ---------------------------------------------------------------------------
__global__ __launch_bounds__(256) void f2h(
    const float* __restrict__ s, __half* __restrict__ d, int n)
{
    int i = (blockIdx.x * 256 + threadIdx.x) * 8;
    if (i + 8 <= n) {
        float4 a = *(const float4*)&s[i];
        float4 b = *(const float4*)&s[i + 4];
        uint4 o = make_uint4(packh2(a.x, a.y), packh2(a.z, a.w),
                             packh2(b.x, b.y), packh2(b.z, b.w));
        *(uint4*)&d[i] = o;
    }
}

// ---------------------------------------------------------------------------
// fp16 mma GEMM (pure-fp16, cp.async double buffer):
//   out = (A @ Bw^T + bias) * oscale
// A:[M,1024] half row-major, Bw:[1024,1024] half row-major.
// 128x128 CTA tile, BK=64, 8 warps each 64x32 via m16n8k16 + ldmatrix.
// MODE 0: out half, head-split [B,H,S,DK]; MODE 1: out float [M,N].
// ---------------------------------------------------------------------------
static constexpr int GTILE = 128 * SH;                 // halves per tile
static constexpr int GEMM_SMEM = 2 * 2 * GTILE * 2;    // 73728 bytes
static constexpr int GNCH = cD / 64;                   // 16 chunks

template<int MODE>
__global__ __launch_bounds__(256, 2) void gemm_h(
    const __half* __restrict__ A, const __half* __restrict__ Bw,
    const float* __restrict__ bias, void* __restrict__ outp, float oscale)
{
    extern __shared__ __half smh[];
    const uint32_t smb = smem_u32(smh);
    const int tid  = threadIdx.x;
    const int wid  = tid >> 5;
    const int lane = tid & 31;
    const int gid  = lane >> 2;
    const int tig  = lane & 3;
    const int m0 = blockIdx.y * 128;
    const int n0 = blockIdx.x * 128;
    const int wm = (wid & 1) * 64;
    const int wn = (wid >> 1) * 32;

    float acc[4][4][4];
    #pragma unroll
    for (int a = 0; a < 4; a++)
        #pragma unroll
        for (int b = 0; b < 4; b++)
            #pragma unroll
            for (int c = 0; c < 4; c++) acc[a][b][c] = 0.f;

    auto cpt = [&](int kt, int buf) {
        const int k0 = kt * 64;
        const uint32_t Ab = smb + (uint32_t)(buf * 2 * GTILE) * 2;
        const uint32_t Bb = Ab + (uint32_t)GTILE * 2;
        #pragma unroll
        for (int it = 0; it < 4; it++) {
            int idx = tid + it * 256, row = idx >> 3, c8 = (idx & 7) * 8;
            uint32_t soff = (uint32_t)((row * SH + c8) * 2);
            cp16(Ab + soff, A  + (size_t)(m0 + row) * cD + k0 + c8);
            cp16(Bb + soff, Bw + (size_t)(n0 + row) * cD + k0 + c8);
        }
    };
    auto comp = [&](int buf) {
        const uint32_t Ab = smb + (uint32_t)(buf * 2 * GTILE) * 2;
        const uint32_t Bb = Ab + (uint32_t)GTILE * 2;
        #pragma unroll
        for (int ks = 0; ks < 4; ks++) {
            const int kk = ks * 16;
            uint32_t af[4][4], bf[4][2];
            #pragma unroll
            for (int mt = 0; mt < 4; mt++) {
                uint32_t a = Ab + (uint32_t)(((wm + mt*16 + (lane & 15)) * SH
                                 + kk + (lane >> 4) * 8) * 2);
                ldsm4(af[mt][0], af[mt][1], af[mt][2], af[mt][3], a);
            }
            #pragma unroll
            for (int g = 0; g < 2; g++) {
                uint32_t a = Bb + (uint32_t)(((wn + g*16 + ((lane >> 4) & 1) * 8
                                 + (lane & 7)) * SH + kk + ((lane >> 3) & 1) * 8) * 2);
                ldsm4(bf[2*g][0], bf[2*g][1], bf[2*g+1][0], bf[2*g+1][1], a);
            }
            #pragma unroll
            for (int mt = 0; mt < 4; mt++)
                #pragma unroll
                for (int nt = 0; nt < 4; nt++)
                    mma_f16(acc[mt][nt], af[mt][0], af[mt][1], af[mt][2],
                            af[mt][3], bf[nt][0], bf[nt][1]);
        }
    };

    cpt(0, 0);
    CP_COMMIT();
    for (int kt = 0; kt < GNCH; kt++) {
        const int buf = kt & 1;
        if (kt + 1 < GNCH) {
            cpt(kt + 1, buf ^ 1);
            CP_COMMIT();
            CP_WAIT(1);
        } else {
            CP_WAIT(0);
        }
        __syncthreads();
        comp(buf);
        __syncthreads();
    }

    #pragma unroll
    for (int mt = 0; mt < 4; mt++) {
        #pragma unroll
        for (int i = 0; i < 2; i++) {
            const int m = m0 + wm + mt*16 + gid + i*8;
            const int bb = m / cS, ss = m % cS;
            #pragma unroll
            for (int nt = 0; nt < 4; nt++) {
                const int n = n0 + wn + nt*8 + 2*tig;
                float2 bv = *(const float2*)&bias[n];
                float v0 = (acc[mt][nt][i*2+0] + bv.x) * oscale;
                float v1 = (acc[mt][nt][i*2+1] + bv.y) * oscale;
                if (MODE == 1) {
                    float* o = (float*)outp;
                    *(float2*)&o[(size_t)m * cD + n] = make_float2(v0, v1);
                } else {
                    __half* o = (__half*)outp;
                    int hh = n / cDK, d0 = n % cDK;
                    size_t base = ((size_t)(bb * cH + hh) * cS + ss) * cDK + d0;
                    *(uint32_t*)&o[base] = packh2(v0, v1);
                }
            }
        }
    }
}

// ---------------------------------------------------------------------------
// fp16 flash attention (base-2 softmax; q pre-scaled by 0.125*log2e).
// BM=128 (8 warps x m16), BN=64 keys, DK=64. cp.async KV double buffer.
// ---------------------------------------------------------------------------
static constexpr int QSH = 128 * SH;     // 9216 halves
static constexpr int KVH = 64 * SH;      // 4608 halves
static constexpr int ATTN_SMEM = (QSH + 4 * KVH) * 2;   // 55296 bytes
static constexpr int NT = cS / 64;       // 32 tiles

__global__ __launch_bounds__(256, 2) void attn_h()
{
    extern __shared__ __half sh[];
    const uint32_t smb = smem_u32(sh);
    const int tid  = threadIdx.x;
    const int wid  = tid >> 5;
    const int lane = tid & 31;
    const int gid  = lane >> 2;
    const int tig  = lane & 3;
    const int q0 = blockIdx.x * 128;
    const int h  = blockIdx.y;
    const int b  = blockIdx.z;

    const size_t head_off = (size_t)(b * cH + h) * cS * cDK;
    const __half* Qh = g_qh + head_off;
    const __half* Kh = g_kh + head_off;
    const __half* Vh = g_vh + head_off;

    #pragma unroll
    for (int it = 0; it < 4; it++) {
        int idx = tid + it * 256, row = idx >> 3, c8 = (idx & 7) * 8;
        *(uint4*)&sh[row * SH + c8] =
            *(const uint4*)&Qh[(size_t)(q0 + row) * cDK + c8];
    }
    __syncthreads();

    uint32_t qf[4][4];
    #pragma unroll
    for (int s = 0; s < 4; s++) {
        uint32_t a = smb + (uint32_t)(((wid*16 + (lane & 15)) * SH
                         + s*16 + (lane >> 4) * 8) * 2);
        ldsm4(qf[s][0], qf[s][1], qf[s][2], qf[s][3], a);
    }

    float o[8][4];
    #pragma unroll
    for (int nt = 0; nt < 8; nt++)
        #pragma unroll
        for (int c = 0; c < 4; c++) o[nt][c] = 0.f;
    float mr0 = -1e30f, mr1 = -1e30f, l0 = 0.f, l1 = 0.f;
    const int r0 = wid * 16 + gid;

    auto cp_tile = [&](int kt, int buf) {
        const __half* Kp = Kh + (size_t)kt * 64 * cDK;
        const __half* Vp = Vh + (size_t)kt * 64 * cDK;
        const uint32_t Kb = smb + (uint32_t)(QSH + buf * 2 * KVH) * 2;
        const uint32_t Vb = Kb + KVH * 2;
        #pragma unroll
        for (int it = 0; it < 2; it++) {
            int idx = tid + it * 256, row = idx >> 3, c8 = (idx & 7) * 8;
            uint32_t soff = (uint32_t)((row * SH + c8) * 2);
            cp16(Kb + soff, Kp + (size_t)row * cDK + c8);
            cp16(Vb + soff, Vp + (size_t)row * cDK + c8);
        }
    };

    cp_tile(0, 0);
    CP_COMMIT();

    for (int kt = 0; kt < NT; kt++) {
        const int buf = kt & 1;
        if (kt + 1 < NT) {
            cp_tile(kt + 1, buf ^ 1);
            CP_COMMIT();
            CP_WAIT(1);
        } else {
            CP_WAIT(0);
        }
        __syncthreads();

        const uint32_t Kb = smb + (uint32_t)(QSH + buf * 2 * KVH) * 2;
        const uint32_t Vb = Kb + KVH * 2;

        float sc[8][4];
        #pragma unroll
        for (int nt = 0; nt < 8; nt++)
            #pragma unroll
            for (int c = 0; c < 4; c++) sc[nt][c] = 0.f;
        #pragma unroll
        for (int s = 0; s < 4; s++) {
            const int kk = s * 16;
            #pragma unroll
            for (int g = 0; g < 4; g++) {
                uint32_t a = Kb + (uint32_t)(((g*16 + ((lane >> 4) & 1) * 8
                                 + (lane & 7)) * SH + kk + ((lane >> 3) & 1) * 8) * 2);
                uint32_t b0, b1, b2, b3;
                ldsm4(b0, b1, b2, b3, a);
                mma_f16(sc[2*g],   qf[s][0], qf[s][1], qf[s][2], qf[s][3], b0, b1);
                mma_f16(sc[2*g+1], qf[s][0], qf[s][1], qf[s][2], qf[s][3], b2, b3);
            }
        }

        float mx0 = -1e30f, mx1 = -1e30f;
        #pragma unroll
        for (int nt = 0; nt < 8; nt++) {
            mx0 = fmaxf(mx0, fmaxf(sc[nt][0], sc[nt][1]));
            mx1 = fmaxf(mx1, fmaxf(sc[nt][2], sc[nt][3]));
        }
        #pragma unroll
        for (int off = 1; off < 4; off <<= 1) {
            mx0 = fmaxf(mx0, __shfl_xor_sync(0xffffffffu, mx0, off));
            mx1 = fmaxf(mx1, __shfl_xor_sync(0xffffffffu, mx1, off));
        }
        const float mn0 = fmaxf(mr0, mx0);
        const float mn1 = fmaxf(mr1, mx1);
        const float cor0 = exp2f(mr0 - mn0);
        const float cor1 = exp2f(mr1 - mn1);
        mr0 = mn0; mr1 = mn1;

        float s0 = 0.f, s1 = 0.f;
        #pragma unroll
        for (int nt = 0; nt < 8; nt++) {
            sc[nt][0] = exp2f(sc[nt][0] - mn0);
            sc[nt][1] = exp2f(sc[nt][1] - mn0);
            sc[nt][2] = exp2f(sc[nt][2] - mn1);
            sc[nt][3] = exp2f(sc[nt][3] - mn1);
            s0 += sc[nt][0] + sc[nt][1];
            s1 += sc[nt][2] + sc[nt][3];
        }
        #pragma unroll
        for (int off = 1; off < 4; off <<= 1) {
            s0 += __shfl_xor_sync(0xffffffffu, s0, off);
            s1 += __shfl_xor_sync(0xffffffffu, s1, off);
        }
        l0 = l0 * cor0 + s0;
        l1 = l1 * cor1 + s1;
        #pragma unroll
        for (int nt = 0; nt < 8; nt++) {
            o[nt][0] *= cor0; o[nt][1] *= cor0;
            o[nt][2] *= cor1; o[nt][3] *= cor1;
        }

        uint32_t pa[4][4];
        #pragma unroll
        for (int s = 0; s < 4; s++) {
            pa[s][0] = packh2(sc[2*s][0],   sc[2*s][1]);
            pa[s][1] = packh2(sc[2*s][2],   sc[2*s][3]);
            pa[s][2] = packh2(sc[2*s+1][0], sc[2*s+1][1]);
            pa[s][3] = packh2(sc[2*s+1][2], sc[2*s+1][3]);
        }

        #pragma unroll
        for (int s = 0; s < 4; s++) {
            #pragma unroll
            for (int g = 0; g < 4; g++) {
                uint32_t a = Vb + (uint32_t)(((s*16 + ((lane >> 3) & 1) * 8
                                 + (lane & 7)) * SH + g*16 + (lane >> 4) * 8) * 2);
                uint32_t b0, b1, b2, b3;
                ldsm4t(b0, b1, b2, b3, a);
                mma_f16(o[2*g],   pa[s][0], pa[s][1], pa[s][2], pa[s][3], b0, b1);
                mma_f16(o[2*g+1], pa[s][0], pa[s][1], pa[s][2], pa[s][3], b2, b3);
            }
        }
        __syncthreads();
    }

    const float inv0 = 1.0f / l0;
    const float inv1 = 1.0f / l1;
    const size_t row0 = (size_t)(b * cS + q0 + r0) * cD + h * cDK;
    const size_t row1 = row0 + 8 * cD;
    #pragma unroll
    for (int nt = 0; nt < 8; nt++) {
        const int d = nt * 8 + 2 * tig;
        *(uint32_t*)&g_ctxh[row0 + d] = packh2(o[nt][0]*inv0, o[nt][1]*inv0);
        *(uint32_t*)&g_ctxh[row1 + d] = packh2(o[nt][2]*inv1, o[nt][3]*inv1);
    }
}

// ---------------------------------------------------------------------------
extern "C" void kernel_launch(void* const* d_in, const int* in_sizes, int n_in,
                              void* d_out, int out_size)
{
    const float* Q  = (const float*)d_in[0];
    const float* K  = (const float*)d_in[1];
    const float* V  = (const float*)d_in[2];
    const float* wq = (const float*)d_in[3];
    const float* bq = (const float*)d_in[4];
    const float* wk = (const float*)d_in[5];
    const float* bk = (const float*)d_in[6];
    const float* wv = (const float*)d_in[7];
    const float* bv = (const float*)d_in[8];
    const float* wo = (const float*)d_in[9];
    const float* bo = (const float*)d_in[10];
    float* out = (float*)d_out;

    __half *pq, *pk, *pv, *pctx, *xq, *xk, *xv, *hwq, *hwk, *hwv, *hwo;
    cudaGetSymbolAddress((void**)&pq,   g_qh);
    cudaGetSymbolAddress((void**)&pk,   g_kh);
    cudaGetSymbolAddress((void**)&pv,   g_vh);
    cudaGetSymbolAddress((void**)&pctx, g_ctxh);
    cudaGetSymbolAddress((void**)&xq,   g_xq);
    cudaGetSymbolAddress((void**)&xk,   g_xk);
    cudaGetSymbolAddress((void**)&xv,   g_xv);
    cudaGetSymbolAddress((void**)&hwq,  g_wq);
    cudaGetSymbolAddress((void**)&hwk,  g_wk);
    cudaGetSymbolAddress((void**)&hwv,  g_wv);
    cudaGetSymbolAddress((void**)&hwo,  g_wo);

    cudaFuncSetAttribute(attn_h,
                         cudaFuncAttributeMaxDynamicSharedMemorySize, ATTN_SMEM);
    cudaFuncSetAttribute((const void*)gemm_h<0>,
                         cudaFuncAttributeMaxDynamicSharedMemorySize, GEMM_SMEM);
    cudaFuncSetAttribute((const void*)gemm_h<1>,
                         cudaFuncAttributeMaxDynamicSharedMemorySize, GEMM_SMEM);

    const int nX = cM * cD;   // 4M
    const int nW = cD * cD;   // 1M
    f2h<<<nX / (8 * 256), 256>>>(Q,  xq,  nX);
    f2h<<<nX / (8 * 256), 256>>>(K,  xk,  nX);
    f2h<<<nX / (8 * 256), 256>>>(V,  xv,  nX);
    f2h<<<nW / (8 * 256), 256>>>(wq, hwq, nW);
    f2h<<<nW / (8 * 256), 256>>>(wk, hwk, nW);
    f2h<<<nW / (8 * 256), 256>>>(wv, hwv, nW);
    f2h<<<nW / (8 * 256), 256>>>(wo, hwo, nW);

    dim3 gg(cD / 128, cM / 128);   // (8, 32)
    // q pre-scaled by 1/sqrt(DK) * log2(e) for base-2 softmax
    const float qscale = 0.125f * 1.4426950408889634f;
    gemm_h<0><<<gg, 256, GEMM_SMEM>>>(xq, hwq, bq, pq, qscale);
    gemm_h<0><<<gg, 256, GEMM_SMEM>>>(xk, hwk, bk, pk, 1.0f);
    gemm_h<0><<<gg, 256, GEMM_SMEM>>>(xv, hwv, bv, pv, 1.0f);
    attn_h<<<dim3(cS/128, cH, cB), 256, ATTN_SMEM>>>();
    gemm_h<1><<<gg, 256, GEMM_SMEM>>>(pctx, hwo, bo, out, 1.0f);
}

// round 7
// speedup vs baseline: 7.0077x; 1.0672x over previous
#include <cuda_runtime.h>
#include <cuda_fp16.h>
#include <cstdint>

static constexpr int cB  = 2;
static constexpr int cS  = 2048;
static constexpr int cD  = 1024;
static constexpr int cH  = 16;
static constexpr int cDK = 64;
static constexpr int cM  = cB * cS;   // 4096
static constexpr int cNX = cM * cD;   // 4,194,304
static constexpr int cNW = cD * cD;   // 1,048,576

// Scratch (allocation-free)
__device__ __half g_xqkv[3*cNX];          // fp16 inputs Q|K|V
__device__ __half g_wqkv[3*cNW];          // fp16 weights wq|wk|wv
__device__ __half g_wo[cNW];              // fp16 wo
__device__ __half g_qkvh[3*cNX];          // projected q|k|v head-split
__device__ __half g_ctxh[cNX];            // attention output [M,D]

// ---------------------------------------------------------------------------
// Helpers
// ---------------------------------------------------------------------------
__device__ __forceinline__ uint32_t smem_u32(const void* p) {
    uint32_t a;
    asm("{ .reg .u64 t; cvta.to.shared.u64 t, %1; cvt.u32.u64 %0, t; }"
        : "=r"(a) : "l"(p));
    return a;
}
__device__ __forceinline__ uint32_t packh2(float lo, float hi) {
    __half2 h = __floats2half2_rn(lo, hi);
    return *reinterpret_cast<uint32_t*>(&h);
}
__device__ __forceinline__ void ldsm4(uint32_t& r0, uint32_t& r1,
                                      uint32_t& r2, uint32_t& r3, uint32_t a) {
    asm volatile("ldmatrix.sync.aligned.m8n8.x4.shared.b16 {%0,%1,%2,%3}, [%4];"
        : "=r"(r0), "=r"(r1), "=r"(r2), "=r"(r3) : "r"(a));
}
__device__ __forceinline__ void ldsm4t(uint32_t& r0, uint32_t& r1,
                                       uint32_t& r2, uint32_t& r3, uint32_t a) {
    asm volatile("ldmatrix.sync.aligned.m8n8.x4.trans.shared.b16 {%0,%1,%2,%3}, [%4];"
        : "=r"(r0), "=r"(r1), "=r"(r2), "=r"(r3) : "r"(a));
}
__device__ __forceinline__ void mma_f16(
    float* c, uint32_t a0, uint32_t a1, uint32_t a2, uint32_t a3,
    uint32_t b0, uint32_t b1)
{
    asm volatile(
        "mma.sync.aligned.m16n8k16.row.col.f32.f16.f16.f32 "
        "{%0,%1,%2,%3}, {%4,%5,%6,%7}, {%8,%9}, {%0,%1,%2,%3};"
        : "+f"(c[0]), "+f"(c[1]), "+f"(c[2]), "+f"(c[3])
        : "r"(a0), "r"(a1), "r"(a2), "r"(a3), "r"(b0), "r"(b1));
}
__device__ __forceinline__ void cp16(uint32_t dst, const void* src) {
    asm volatile("cp.async.ca.shared.global [%0], [%1], 16;"
        :: "r"(dst), "l"(src));
}
#define CP_COMMIT() asm volatile("cp.async.commit_group;" ::: "memory")
#define CP_WAIT(n)  asm volatile("cp.async.wait_group %0;" :: "n"(n) : "memory")

static constexpr int SH = 72;   // smem stride in halves per 64-half row

// ---------------------------------------------------------------------------
// Batched fp32->fp16 convert: Q,K,V -> g_xqkv; wq,wk,wv -> g_wqkv; wo -> g_wo
// ---------------------------------------------------------------------------
struct F2HArgs { const float* s[7]; };
static constexpr int VX = cNX / 8;        // 524288 vec8 per input tensor
static constexpr int VW = cNW / 8;        // 131072 vec8 per weight
static constexpr int F2H_BLOCKS = (3 * VX + 4 * VW) / 256;   // 8192

__global__ __launch_bounds__(256) void f2h_all(F2HArgs a)
{
    int vid = blockIdx.x * 256 + threadIdx.x;
    const float* s;
    __half* d;
    if (vid < 3 * VX) {
        int z = vid / VX;
        size_t off = (size_t)(vid - z * VX) * 8;
        s = a.s[z] + off;
        d = g_xqkv + (size_t)z * cNX + off;
    } else {
        int w = (vid - 3 * VX) / VW;
        size_t off = (size_t)(vid - 3 * VX - w * VW) * 8;
        s = a.s[3 + w] + off;
        d = (w < 3 ? g_wqkv + (size_t)w * cNW : g_wo) + off;
    }
    float4 x = *(const float4*)s;
    float4 y = *(const float4*)(s + 4);
    *(uint4*)d = make_uint4(packh2(x.x, x.y), packh2(x.z, x.w),
                            packh2(y.x, y.y), packh2(y.z, y.w));
}

// ---------------------------------------------------------------------------
// fp16 mma GEMM core (cp.async, single-barrier pipeline):
//   out = (A @ W^T + bias) * oscale
// 128x128 CTA tile, BK=64, 8 warps each 64x32 via m16n8k16 + ldmatrix.
// ---------------------------------------------------------------------------
static constexpr int GTILE = 128 * SH;                 // halves per tile
static constexpr int GEMM_SMEM = 2 * 2 * GTILE * 2;    // 73728 bytes
static constexpr int GNCH = cD / 64;                   // 16 chunks

template<int MODE>
__device__ __forceinline__ void gemm_core(
    const __half* __restrict__ A, const __half* __restrict__ W,
    const float* __restrict__ bias, void* __restrict__ outp, float oscale)
{
    extern __shared__ __half smh[];
    const uint32_t smb = smem_u32(smh);
    const int tid  = threadIdx.x;
    const int wid  = tid >> 5;
    const int lane = tid & 31;
    const int gid  = lane >> 2;
    const int tig  = lane & 3;
    const int m0 = blockIdx.y * 128;
    const int n0 = blockIdx.x * 128;
    const int wm = (wid & 1) * 64;
    const int wn = (wid >> 1) * 32;

    float acc[4][4][4];
    #pragma unroll
    for (int a = 0; a < 4; a++)
        #pragma unroll
        for (int b = 0; b < 4; b++)
            #pragma unroll
            for (int c = 0; c < 4; c++) acc[a][b][c] = 0.f;

    auto cpt = [&](int kt, int buf) {
        const int k0 = kt * 64;
        const uint32_t Ab = smb + (uint32_t)(buf * 2 * GTILE) * 2;
        const uint32_t Bb = Ab + (uint32_t)GTILE * 2;
        #pragma unroll
        for (int it = 0; it < 4; it++) {
            int idx = tid + it * 256, row = idx >> 3, c8 = (idx & 7) * 8;
            uint32_t soff = (uint32_t)((row * SH + c8) * 2);
            cp16(Ab + soff, A + (size_t)(m0 + row) * cD + k0 + c8);
            cp16(Bb + soff, W + (size_t)(n0 + row) * cD + k0 + c8);
        }
        CP_COMMIT();
    };
    auto comp = [&](int buf) {
        const uint32_t Ab = smb + (uint32_t)(buf * 2 * GTILE) * 2;
        const uint32_t Bb = Ab + (uint32_t)GTILE * 2;
        #pragma unroll
        for (int ks = 0; ks < 4; ks++) {
            const int kk = ks * 16;
            uint32_t af[4][4], bf[4][2];
            #pragma unroll
            for (int mt = 0; mt < 4; mt++) {
                uint32_t a = Ab + (uint32_t)(((wm + mt*16 + (lane & 15)) * SH
                                 + kk + (lane >> 4) * 8) * 2);
                ldsm4(af[mt][0], af[mt][1], af[mt][2], af[mt][3], a);
            }
            #pragma unroll
            for (int g = 0; g < 2; g++) {
                uint32_t a = Bb + (uint32_t)(((wn + g*16 + ((lane >> 4) & 1) * 8
                                 + (lane & 7)) * SH + kk + ((lane >> 3) & 1) * 8) * 2);
                ldsm4(bf[2*g][0], bf[2*g][1], bf[2*g+1][0], bf[2*g+1][1], a);
            }
            #pragma unroll
            for (int mt = 0; mt < 4; mt++)
                #pragma unroll
                for (int nt = 0; nt < 4; nt++)
                    mma_f16(acc[mt][nt], af[mt][0], af[mt][1], af[mt][2],
                            af[mt][3], bf[nt][0], bf[nt][1]);
        }
    };

    cpt(0, 0);
    for (int kt = 0; kt < GNCH; kt++) {
        const int buf = kt & 1;
        CP_WAIT(0);          // this warp's cp(kt) done
        __syncthreads();     // => all warps' cp(kt) done; compute(kt-1) done
        if (kt + 1 < GNCH) cpt(kt + 1, buf ^ 1);   // overwrites slot of kt-1
        comp(buf);
    }

    #pragma unroll
    for (int mt = 0; mt < 4; mt++) {
        #pragma unroll
        for (int i = 0; i < 2; i++) {
            const int m = m0 + wm + mt*16 + gid + i*8;
            const int bb = m / cS, ss = m % cS;
            #pragma unroll
            for (int nt = 0; nt < 4; nt++) {
                const int n = n0 + wn + nt*8 + 2*tig;
                float2 bv = *(const float2*)&bias[n];
                float v0 = (acc[mt][nt][i*2+0] + bv.x) * oscale;
                float v1 = (acc[mt][nt][i*2+1] + bv.y) * oscale;
                if (MODE == 1) {
                    float* o = (float*)outp;
                    *(float2*)&o[(size_t)m * cD + n] = make_float2(v0, v1);
                } else {
                    __half* o = (__half*)outp;
                    int hh = n / cDK, d0 = n % cDK;
                    size_t base = ((size_t)(bb * cH + hh) * cS + ss) * cDK + d0;
                    *(uint32_t*)&o[base] = packh2(v0, v1);
                }
            }
        }
    }
}

// Batched QKV projection: z in {0,1,2} selects input/weight/bias/output.
__global__ __launch_bounds__(256, 2) void gemm_qkv(
    const float* bq, const float* bk, const float* bv, float qscale)
{
    const int z = blockIdx.z;
    const __half* A = g_xqkv + (size_t)z * cNX;
    const __half* W = g_wqkv + (size_t)z * cNW;
    const float* bias = (z == 0) ? bq : (z == 1 ? bk : bv);
    __half* out = g_qkvh + (size_t)z * cNX;
    gemm_core<0>(A, W, bias, out, z == 0 ? qscale : 1.0f);
}

// Output projection: ctx @ wo^T + bo -> float out
__global__ __launch_bounds__(256, 2) void gemm_o(
    const float* bo, float* out)
{
    gemm_core<1>(g_ctxh, g_wo, bo, out, 1.0f);
}

// ---------------------------------------------------------------------------
// fp16 flash attention (base-2 softmax; q pre-scaled by 0.125*log2e).
// BM=128 (8 warps x m16), BN=64 keys, DK=64. cp.async KV double buffer,
// single barrier per tile.
// ---------------------------------------------------------------------------
static constexpr int QSH = 128 * SH;     // 9216 halves
static constexpr int KVH = 64 * SH;      // 4608 halves
static constexpr int ATTN_SMEM = (QSH + 4 * KVH) * 2;   // 55296 bytes
static constexpr int NT = cS / 64;       // 32 tiles

__global__ __launch_bounds__(256, 2) void attn_h()
{
    extern __shared__ __half sh[];
    const uint32_t smb = smem_u32(sh);
    const int tid  = threadIdx.x;
    const int wid  = tid >> 5;
    const int lane = tid & 31;
    const int gid  = lane >> 2;
    const int tig  = lane & 3;
    const int q0 = blockIdx.x * 128;
    const int h  = blockIdx.y;
    const int b  = blockIdx.z;

    const size_t head_off = (size_t)(b * cH + h) * cS * cDK;
    const __half* Qh = g_qkvh + head_off;
    const __half* Kh = g_qkvh + cNX + head_off;
    const __half* Vh = g_qkvh + 2 * (size_t)cNX + head_off;

    auto cp_tile = [&](int kt, int buf) {
        const __half* Kp = Kh + (size_t)kt * 64 * cDK;
        const __half* Vp = Vh + (size_t)kt * 64 * cDK;
        const uint32_t Kb = smb + (uint32_t)(QSH + buf * 2 * KVH) * 2;
        const uint32_t Vb = Kb + KVH * 2;
        #pragma unroll
        for (int it = 0; it < 2; it++) {
            int idx = tid + it * 256, row = idx >> 3, c8 = (idx & 7) * 8;
            uint32_t soff = (uint32_t)((row * SH + c8) * 2);
            cp16(Kb + soff, Kp + (size_t)row * cDK + c8);
            cp16(Vb + soff, Vp + (size_t)row * cDK + c8);
        }
        CP_COMMIT();
    };

    // Kick off KV tile 0 before staging Q (more latency cover)
    cp_tile(0, 0);

    #pragma unroll
    for (int it = 0; it < 4; it++) {
        int idx = tid + it * 256, row = idx >> 3, c8 = (idx & 7) * 8;
        *(uint4*)&sh[row * SH + c8] =
            *(const uint4*)&Qh[(size_t)(q0 + row) * cDK + c8];
    }
    __syncthreads();

    uint32_t qf[4][4];
    #pragma unroll
    for (int s = 0; s < 4; s++) {
        uint32_t a = smb + (uint32_t)(((wid*16 + (lane & 15)) * SH
                         + s*16 + (lane >> 4) * 8) * 2);
        ldsm4(qf[s][0], qf[s][1], qf[s][2], qf[s][3], a);
    }

    float o[8][4];
    #pragma unroll
    for (int nt = 0; nt < 8; nt++)
        #pragma unroll
        for (int c = 0; c < 4; c++) o[nt][c] = 0.f;
    float mr0 = -1e30f, mr1 = -1e30f, l0 = 0.f, l1 = 0.f;
    const int r0 = wid * 16 + gid;

    for (int kt = 0; kt < NT; kt++) {
        const int buf = kt & 1;
        CP_WAIT(0);
        __syncthreads();
        if (kt + 1 < NT) cp_tile(kt + 1, buf ^ 1);

        const uint32_t Kb = smb + (uint32_t)(QSH + buf * 2 * KVH) * 2;
        const uint32_t Vb = Kb + KVH * 2;

        float sc[8][4];
        #pragma unroll
        for (int nt = 0; nt < 8; nt++)
            #pragma unroll
            for (int c = 0; c < 4; c++) sc[nt][c] = 0.f;
        #pragma unroll
        for (int s = 0; s < 4; s++) {
            const int kk = s * 16;
            #pragma unroll
            for (int g = 0; g < 4; g++) {
                uint32_t a = Kb + (uint32_t)(((g*16 + ((lane >> 4) & 1) * 8
                                 + (lane & 7)) * SH + kk + ((lane >> 3) & 1) * 8) * 2);
                uint32_t b0, b1, b2, b3;
                ldsm4(b0, b1, b2, b3, a);
                mma_f16(sc[2*g],   qf[s][0], qf[s][1], qf[s][2], qf[s][3], b0, b1);
                mma_f16(sc[2*g+1], qf[s][0], qf[s][1], qf[s][2], qf[s][3], b2, b3);
            }
        }

        float mx0 = -1e30f, mx1 = -1e30f;
        #pragma unroll
        for (int nt = 0; nt < 8; nt++) {
            mx0 = fmaxf(mx0, fmaxf(sc[nt][0], sc[nt][1]));
            mx1 = fmaxf(mx1, fmaxf(sc[nt][2], sc[nt][3]));
        }
        #pragma unroll
        for (int off = 1; off < 4; off <<= 1) {
            mx0 = fmaxf(mx0, __shfl_xor_sync(0xffffffffu, mx0, off));
            mx1 = fmaxf(mx1, __shfl_xor_sync(0xffffffffu, mx1, off));
        }
        const float mn0 = fmaxf(mr0, mx0);
        const float mn1 = fmaxf(mr1, mx1);
        const float cor0 = exp2f(mr0 - mn0);
        const float cor1 = exp2f(mr1 - mn1);
        mr0 = mn0; mr1 = mn1;

        float s0 = 0.f, s1 = 0.f;
        #pragma unroll
        for (int nt = 0; nt < 8; nt++) {
            sc[nt][0] = exp2f(sc[nt][0] - mn0);
            sc[nt][1] = exp2f(sc[nt][1] - mn0);
            sc[nt][2] = exp2f(sc[nt][2] - mn1);
            sc[nt][3] = exp2f(sc[nt][3] - mn1);
            s0 += sc[nt][0] + sc[nt][1];
            s1 += sc[nt][2] + sc[nt][3];
        }
        #pragma unroll
        for (int off = 1; off < 4; off <<= 1) {
            s0 += __shfl_xor_sync(0xffffffffu, s0, off);
            s1 += __shfl_xor_sync(0xffffffffu, s1, off);
        }
        l0 = l0 * cor0 + s0;
        l1 = l1 * cor1 + s1;
        #pragma unroll
        for (int nt = 0; nt < 8; nt++) {
            o[nt][0] *= cor0; o[nt][1] *= cor0;
            o[nt][2] *= cor1; o[nt][3] *= cor1;
        }

        uint32_t pa[4][4];
        #pragma unroll
        for (int s = 0; s < 4; s++) {
            pa[s][0] = packh2(sc[2*s][0],   sc[2*s][1]);
            pa[s][1] = packh2(sc[2*s][2],   sc[2*s][3]);
            pa[s][2] = packh2(sc[2*s+1][0], sc[2*s+1][1]);
            pa[s][3] = packh2(sc[2*s+1][2], sc[2*s+1][3]);
        }

        #pragma unroll
        for (int s = 0; s < 4; s++) {
            #pragma unroll
            for (int g = 0; g < 4; g++) {
                uint32_t a = Vb + (uint32_t)(((s*16 + ((lane >> 3) & 1) * 8
                                 + (lane & 7)) * SH + g*16 + (lane >> 4) * 8) * 2);
                uint32_t b0, b1, b2, b3;
                ldsm4t(b0, b1, b2, b3, a);
                mma_f16(o[2*g],   pa[s][0], pa[s][1], pa[s][2], pa[s][3], b0, b1);
                mma_f16(o[2*g+1], pa[s][0], pa[s][1], pa[s][2], pa[s][3], b2, b3);
            }
        }
    }

    const float inv0 = 1.0f / l0;
    const float inv1 = 1.0f / l1;
    const size_t row0 = (size_t)(b * cS + q0 + r0) * cD + h * cDK;
    const size_t row1 = row0 + 8 * cD;
    #pragma unroll
    for (int nt = 0; nt < 8; nt++) {
        const int d = nt * 8 + 2 * tig;
        *(uint32_t*)&g_ctxh[row0 + d] = packh2(o[nt][0]*inv0, o[nt][1]*inv0);
        *(uint32_t*)&g_ctxh[row1 + d] = packh2(o[nt][2]*inv1, o[nt][3]*inv1);
    }
}

// ---------------------------------------------------------------------------
extern "C" void kernel_launch(void* const* d_in, const int* in_sizes, int n_in,
                              void* d_out, int out_size)
{
    const float* Q  = (const float*)d_in[0];
    const float* K  = (const float*)d_in[1];
    const float* V  = (const float*)d_in[2];
    const float* wq = (const float*)d_in[3];
    const float* bq = (const float*)d_in[4];
    const float* wk = (const float*)d_in[5];
    const float* bk = (const float*)d_in[6];
    const float* wv = (const float*)d_in[7];
    const float* bv = (const float*)d_in[8];
    const float* wo = (const float*)d_in[9];
    const float* bo = (const float*)d_in[10];
    float* out = (float*)d_out;

    cudaFuncSetAttribute(attn_h,
                         cudaFuncAttributeMaxDynamicSharedMemorySize, ATTN_SMEM);
    cudaFuncSetAttribute(gemm_qkv,
                         cudaFuncAttributeMaxDynamicSharedMemorySize, GEMM_SMEM);
    cudaFuncSetAttribute(gemm_o,
                         cudaFuncAttributeMaxDynamicSharedMemorySize, GEMM_SMEM);

    F2HArgs fa;
    fa.s[0] = Q;  fa.s[1] = K;  fa.s[2] = V;
    fa.s[3] = wq; fa.s[4] = wk; fa.s[5] = wv; fa.s[6] = wo;
    f2h_all<<<F2H_BLOCKS, 256>>>(fa);

    const float qscale = 0.125f * 1.4426950408889634f;   // 1/sqrt(64) * log2e
    dim3 gq(cD / 128, cM / 128, 3);   // (8, 32, 3)
    gemm_qkv<<<gq, 256, GEMM_SMEM>>>(bq, bk, bv, qscale);
    attn_h<<<dim3(cS/128, cH, cB), 256, ATTN_SMEM>>>();
    dim3 go(cD / 128, cM / 128);      // (8, 32)
    gemm_o<<<go, 256, GEMM_SMEM>>>(bo, out);
}